// round 15
// baseline (speedup 1.0000x reference)
#include <cuda_runtime.h>
#include <cuda_bf16.h>
#include <cstdint>

// ---------------------------------------------------------------------------
// Scratch (device globals — no allocation allowed)
// ---------------------------------------------------------------------------
__device__ float g_h1[16*64*128*128];          // enc1 out / dec2 out (reused)
__device__ float g_h2[16*128*64*64];           // enc2 out / dec1 out (reused)
__device__ float g_h3[16*256*64*64];           // enc3 out
__device__ float g_z [16*256*64*64];           // enc4 out (z) / quantized NCHW (reused)
__device__ float g_resid[65536*256];
__device__ float g_qsum [65536*256];
__device__ double g_loss[4];
__device__ float g_cnorm[4*1024];
__device__ unsigned g_rowmin[4*65536];
__device__ int g_cand[65536*16];               // per-row candidate indices
__device__ int g_ccnt[4*65536];                // per-row candidate counts
__device__ float g_w4p[64*16*4];               // dec_w4 repacked [ci][pt(16)][co pad 4]
__device__ float g_wt[1313792];                // conv weights repacked [tap][ci][co]
__device__ float g_wtT[196608];                // convT weights [parity][tap][ci][co]
__device__ float g_d3[16*64*256*256];          // dec3 out; ALSO the 65536x1024 D (bf16)

// ---------------------------------------------------------------------------
// tf32 helpers (approximate Phase-A path only; correctness never depends on it)
// ---------------------------------------------------------------------------
__device__ __forceinline__ uint32_t f2tf(float f) {
    uint32_t u;
    asm("cvt.rna.tf32.f32 %0, %1;" : "=r"(u) : "f"(f));
    return u;
}

__device__ __forceinline__ void mma_tf32(float* c, const uint32_t* a,
                                         uint32_t b0, uint32_t b1) {
    asm volatile(
        "mma.sync.aligned.m16n8k8.row.col.f32.tf32.tf32.f32 "
        "{%0,%1,%2,%3},{%4,%5,%6,%7},{%8,%9},{%0,%1,%2,%3};"
        : "+f"(c[0]), "+f"(c[1]), "+f"(c[2]), "+f"(c[3])
        : "r"(a[0]), "r"(a[1]), "r"(a[2]), "r"(a[3]), "r"(b0), "r"(b1));
}

// order-preserving float <-> uint32 (for atomicMin)
__device__ __forceinline__ unsigned fenc(float d) {
    unsigned u = __float_as_uint(d);
    return (u & 0x80000000u) ? ~u : (u | 0x80000000u);
}
__device__ __forceinline__ float fdec(unsigned e) {
    unsigned u = (e & 0x80000000u) ? (e & 0x7FFFFFFFu) : ~e;
    return __uint_as_float(u);
}

static const int PLW = 128*33;   // one smem plane in words (stride 33: conflict-free)

// ---------------------------------------------------------------------------
// Phase A: approximate distance matrix, single tf32 MMA, D stored as bf16.
// Per-row min -> rowmin (atomicMin). Entries within tilemin+0.03 pushed to the
// per-row candidate list (capacity 16; overflow handled by Phase-B fallback).
// ---------------------------------------------------------------------------
__global__ __launch_bounds__(256)
void vq_gemm_approx(const float* __restrict__ R, const float* __restrict__ cb,
                    const float* __restrict__ cn, __nv_bfloat16* __restrict__ D,
                    unsigned* __restrict__ rowmin,
                    int* __restrict__ cand, int* __restrict__ ccnt)
{
    extern __shared__ uint32_t dyn[];
    uint32_t* sA = dyn;
    uint32_t* sB = dyn + PLW;
    unsigned* sMin = (unsigned*)(dyn + 2*PLW);

    const int tid  = threadIdx.x;
    const int lane = tid & 31;
    const int warp = tid >> 5;
    const int wm = warp & 1;
    const int wn = warp >> 1;
    const int m0 = blockIdx.x << 7;
    const int n0 = blockIdx.y << 7;

    float acc[4][4][4];
#pragma unroll
    for (int i = 0; i < 4; i++)
#pragma unroll
        for (int j = 0; j < 4; j++)
#pragma unroll
            for (int k = 0; k < 4; k++) acc[i][j][k] = 0.f;

    if (tid < 128) sMin[tid] = 0xFFFFFFFFu;

    for (int k0 = 0; k0 < 256; k0 += 32) {
#pragma unroll
        for (int i = 0; i < 4; i++) {
            int idx4 = tid + i*256;
            int m  = idx4 >> 3;
            int kq = idx4 & 7;
            int oa = m*33 + kq*4;
            float4 a = *(const float4*)(R  + (size_t)(m0 + m)*256 + k0 + kq*4);
            sA[oa+0] = f2tf(a.x); sA[oa+1] = f2tf(a.y);
            sA[oa+2] = f2tf(a.z); sA[oa+3] = f2tf(a.w);
            float4 b = *(const float4*)(cb + (size_t)(n0 + m)*256 + k0 + kq*4);
            sB[oa+0] = f2tf(b.x); sB[oa+1] = f2tf(b.y);
            sB[oa+2] = f2tf(b.z); sB[oa+3] = f2tf(b.w);
        }
        __syncthreads();

#pragma unroll
        for (int ks = 0; ks < 4; ks++) {
            const int kb = ks*8 + (lane & 3);
            uint32_t bf[4][2];
#pragma unroll
            for (int fn = 0; fn < 4; fn++) {
                int n = wn*32 + fn*8 + (lane >> 2);
                bf[fn][0] = sB[n*33 + kb];  bf[fn][1] = sB[n*33 + kb + 4];
            }
#pragma unroll
            for (int fm = 0; fm < 4; fm++) {
                int r = wm*64 + fm*16 + (lane >> 2);
                uint32_t af[4];
                af[0] = sA[r*33 + kb];     af[1] = sA[(r+8)*33 + kb];
                af[2] = sA[r*33 + kb+4];   af[3] = sA[(r+8)*33 + kb+4];
#pragma unroll
                for (int fn = 0; fn < 4; fn++)
                    mma_tf32(acc[fm][fn], af, bf[fn][0], bf[fn][1]);
            }
        }
        __syncthreads();
    }

    float cnv[4][2];
#pragma unroll
    for (int fn = 0; fn < 4; fn++) {
        int col = n0 + wn*32 + fn*8 + 2*(lane & 3);
        cnv[fn][0] = cn[col];
        cnv[fn][1] = cn[col + 1];
    }
    // pass 1: D store + tile-local row min
#pragma unroll
    for (int fm = 0; fm < 4; fm++) {
#pragma unroll
        for (int h = 0; h < 2; h++) {
            int rl = wm*64 + fm*16 + (lane >> 2) + h*8;
            int rg = m0 + rl;
            float mn = 3.402823466e38f;
#pragma unroll
            for (int fn = 0; fn < 4; fn++) {
                int col = n0 + wn*32 + fn*8 + 2*(lane & 3);
                float vx = cnv[fn][0] - 2.f*acc[fm][fn][h*2 + 0];
                float vy = cnv[fn][1] - 2.f*acc[fm][fn][h*2 + 1];
                mn = fminf(mn, fminf(vx, vy));
                *(__nv_bfloat162*)(D + (size_t)rg*1024 + col) =
                    __floats2bfloat162_rn(vx, vy);
            }
            atomicMin(&sMin[rl], fenc(mn));
        }
    }
    __syncthreads();
    if (tid < 128) atomicMin(&rowmin[m0 + tid], sMin[tid]);

    // pass 2: push candidates within tilemin + 0.03 (provably superset of the
    // global-min window for this tile's columns)
#pragma unroll
    for (int fm = 0; fm < 4; fm++) {
#pragma unroll
        for (int h = 0; h < 2; h++) {
            int rl = wm*64 + fm*16 + (lane >> 2) + h*8;
            int rg = m0 + rl;
            float th = fdec(sMin[rl]) + 0.03f;
#pragma unroll
            for (int fn = 0; fn < 4; fn++) {
                int col = n0 + wn*32 + fn*8 + 2*(lane & 3);
                float vx = cnv[fn][0] - 2.f*acc[fm][fn][h*2 + 0];
                float vy = cnv[fn][1] - 2.f*acc[fm][fn][h*2 + 1];
                if (vx <= th) {
                    int pos = atomicAdd(&ccnt[rg], 1);
                    if (pos < 16) cand[(size_t)rg*16 + pos] = col;
                }
                if (vy <= th) {
                    int pos = atomicAdd(&ccnt[rg], 1);
                    if (pos < 16) cand[(size_t)rg*16 + pos] = col + 1;
                }
            }
        }
    }
}

// init rowmin (4x65536) to +inf and ccnt (4x65536) to 0
__global__ void init_vq(unsigned* rowmin, int* ccnt) {
    int i = blockIdx.x*1024 + threadIdx.x;
    rowmin[i] = 0xFFFFFFFFu;
    ccnt[i]   = 0;
}

// ---------------------------------------------------------------------------
// Phase B: one warp per token. Fast path: rescore the candidate list exactly
// (order-independent lowest-index tie-break). Fallback on overflow: full
// bf16x2 batched scan of D. Fused vq_update.
// ---------------------------------------------------------------------------
__global__ __launch_bounds__(256)
void vq_select_update(const __nv_bfloat16* __restrict__ D, const float* __restrict__ cb,
                      const float* __restrict__ cn,
                      const unsigned* __restrict__ rowmin,
                      const int* __restrict__ cand, const int* __restrict__ ccnt,
                      float* __restrict__ resid, float* __restrict__ qsum,
                      float* __restrict__ idx_out, int stage,
                      double* __restrict__ lossAcc)
{
    __shared__ double sLoss[8];
    const int warp = threadIdx.x >> 5;
    const int lane = threadIdx.x & 31;
    const int t = blockIdx.x*8 + warp;

    float4 r0 = *(const float4*)(resid + (size_t)t*256 + lane*8);
    float4 r1 = *(const float4*)(resid + (size_t)t*256 + lane*8 + 4);

    float bestd = 3.402823466e38f;
    int   bestn = 0x7FFFFFFF;

    auto rescore = [&](int j) {
        const float* c = cb + (size_t)j*256;
        float4 c0 = *(const float4*)(c + lane*8);
        float4 c1 = *(const float4*)(c + lane*8 + 4);
        float dot = r0.x*c0.x + r0.y*c0.y + r0.z*c0.z + r0.w*c0.w
                  + r1.x*c1.x + r1.y*c1.y + r1.z*c1.z + r1.w*c1.w;
#pragma unroll
        for (int o = 16; o; o >>= 1)
            dot += __shfl_xor_sync(0xffffffffu, dot, o);
        float de = cn[j] - 2.f*dot;
        if (de < bestd || (de == bestd && j < bestn)) { bestd = de; bestn = j; }
    };

    const int cnt = ccnt[t];
    if (cnt <= 16) {
        const int* cl = cand + (size_t)t*16;
        for (int i = 0; i < cnt; i++) rescore(cl[i]);
    } else {
        // overflow fallback: full scan (rare)
        const __nv_bfloat16* drow = D + (size_t)t*1024;
        const float thr = fdec(rowmin[t]) + 0.03f;
#pragma unroll
        for (int j0 = 0; j0 < 1024; j0 += 256) {
            float2 dd[4];
#pragma unroll
            for (int u = 0; u < 4; u++) {
                __nv_bfloat162 dv2 =
                    *(const __nv_bfloat162*)(drow + j0 + u*64 + lane*2);
                dd[u] = __bfloat1622float2(dv2);
            }
#pragma unroll
            for (int u = 0; u < 4; u++) {
                unsigned me = __ballot_sync(0xffffffffu, dd[u].x <= thr);
                unsigned mo = __ballot_sync(0xffffffffu, dd[u].y <= thr);
                while (me) { int s = __ffs(me) - 1; me &= me - 1; rescore(j0 + u*64 + 2*s); }
                while (mo) { int s = __ffs(mo) - 1; mo &= mo - 1; rescore(j0 + u*64 + 2*s + 1); }
            }
        }
    }

    const float* q = cb + (size_t)bestn*256;
    float4 q0 = *(const float4*)(q + lane*8);
    float4 q1 = *(const float4*)(q + lane*8 + 4);
    float4 s0 = *(float4*)(qsum + (size_t)t*256 + lane*8);
    float4 s1 = *(float4*)(qsum + (size_t)t*256 + lane*8 + 4);

    float ls = 0.f;
    {
        float d;
        d = q0.x-r0.x; ls += d*d;  d = q0.y-r0.y; ls += d*d;
        d = q0.z-r0.z; ls += d*d;  d = q0.w-r0.w; ls += d*d;
        d = q1.x-r1.x; ls += d*d;  d = q1.y-r1.y; ls += d*d;
        d = q1.z-r1.z; ls += d*d;  d = q1.w-r1.w; ls += d*d;
    }
    s0.x += q0.x; s0.y += q0.y; s0.z += q0.z; s0.w += q0.w;
    s1.x += q1.x; s1.y += q1.y; s1.z += q1.z; s1.w += q1.w;
    r0.x -= q0.x; r0.y -= q0.y; r0.z -= q0.z; r0.w -= q0.w;
    r1.x -= q1.x; r1.y -= q1.y; r1.z -= q1.z; r1.w -= q1.w;
    *(float4*)(qsum  + (size_t)t*256 + lane*8)     = s0;
    *(float4*)(qsum  + (size_t)t*256 + lane*8 + 4) = s1;
    *(float4*)(resid + (size_t)t*256 + lane*8)     = r0;
    *(float4*)(resid + (size_t)t*256 + lane*8 + 4) = r1;

#pragma unroll
    for (int o = 16; o; o >>= 1) ls += __shfl_down_sync(0xffffffffu, ls, o);
    if (lane == 0) {
        sLoss[warp] = (double)ls;
        idx_out[(t >> 12)*16384 + stage*4096 + (t & 4095)] = (float)bestn;
    }
    __syncthreads();
    if (threadIdx.x == 0) {
        double tot = 0.0;
#pragma unroll
        for (int w = 0; w < 8; w++) tot += sLoss[w];
        atomicAdd(lossAcc + stage, tot);
    }
}

// ---------------------------------------------------------------------------
// enc1 (4x4 s2 p1, Cin=3 -> Cout=64) as implicit GEMM. M=128 px (one output
// row), N=64, K=48 (16 taps x 3 ci), single smem stage. Coalesced stores.
// ---------------------------------------------------------------------------
__global__ __launch_bounds__(256)
void conv1_ffma(const float* __restrict__ in, const float* __restrict__ wt,
                const float* __restrict__ bias, float* __restrict__ out)
{
    __shared__ float sA[48*128];
    __shared__ float sB[48*64];
    const int tid = threadIdx.x;
    const int tx = tid & 31;
    const int ty = tid >> 5;
    const int b  = blockIdx.x >> 7;
    const int yr = blockIdx.x & 127;

    for (int idx = tid; idx < 48*128; idx += 256) {
        int k  = idx >> 7, px = idx & 127;
        int tap = k/3, ci = k - tap*3;
        int kh = tap >> 2, kw = tap & 3;
        int iy = yr*2 + kh - 1;
        int ix = px*2 + kw - 1;
        float v = 0.f;
        if ((unsigned)iy < 256u && (unsigned)ix < 256u)
            v = in[((size_t)(b*3 + ci)*256 + iy)*256 + ix];
        sA[idx] = v;
    }
    for (int idx = tid; idx < 48*64; idx += 256)
        sB[idx] = wt[idx];
    __syncthreads();

    float acc[4][8];
#pragma unroll
    for (int i = 0; i < 4; i++)
#pragma unroll
        for (int j = 0; j < 8; j++) acc[i][j] = 0.f;

#pragma unroll
    for (int kk = 0; kk < 48; kk++) {
        float av[4];
#pragma unroll
        for (int i = 0; i < 4; i++) av[i] = sA[kk*128 + tx + 32*i];
        float4 b0 = *(const float4*)&sB[kk*64 + ty*8];
        float4 b1 = *(const float4*)&sB[kk*64 + ty*8 + 4];
        float bv[8] = {b0.x,b0.y,b0.z,b0.w,b1.x,b1.y,b1.z,b1.w};
#pragma unroll
        for (int i = 0; i < 4; i++)
#pragma unroll
            for (int j = 0; j < 8; j++) acc[i][j] += av[i]*bv[j];
    }

#pragma unroll
    for (int j = 0; j < 8; j++) {
        int co = ty*8 + j;
        float bv = bias[co];
        float* p = out + ((size_t)(b*64 + co)*128 + yr)*128;
#pragma unroll
        for (int i = 0; i < 4; i++)
            p[tx + 32*i] = fmaxf(acc[i][j] + bv, 0.f);
    }
}

// ---------------------------------------------------------------------------
// Implicit-GEMM FFMA conv (3x3 s1 or 4x4 s2, pad 1). Output 64x64 per image.
// Double-buffered smem, register-staged prefetch, single sync per chunk.
// ---------------------------------------------------------------------------
template<int KSZ, int S>
__global__ __launch_bounds__(256, 2)
void conv_ffma(const float* __restrict__ in, const float* __restrict__ wt,
               const float* __restrict__ bias, float* __restrict__ out,
               int Cin, int Hin, int Win, int Cout, int relu)
{
    __shared__ float sA[2][16*128];
    __shared__ float sB[2][16*128];
    const int tid = threadIdx.x;
    const int tx = tid & 15;
    const int ty = tid >> 4;
    const int m0  = blockIdx.x << 7;
    const int co0 = blockIdx.y << 7;
    const int b   = m0 >> 12;
    const int y0  = (m0 & 4095) >> 6;
    const int cpt = Cin >> 4;
    const int NCH = KSZ*KSZ*cpt;

    float acc[8][8];
#pragma unroll
    for (int i = 0; i < 8; i++)
#pragma unroll
        for (int j = 0; j < 8; j++) acc[i][j] = 0.f;

    float ra[8], rb[8];

    auto loadc = [&](int q) {
        int tap = q / cpt;
        int ci0 = (q - tap*cpt) << 4;
        int dy = tap/KSZ - 1, dx = tap%KSZ - 1;
#pragma unroll
        for (int v = 0; v < 8; v++) {
            int idx = tid + v*256;
            int ci = idx >> 7, pix = idx & 127;
            int iy = (y0 + (pix >> 6))*S + dy;
            int ix = (pix & 63)*S + dx;
            float val = 0.f;
            if ((unsigned)iy < (unsigned)Hin && (unsigned)ix < (unsigned)Win)
                val = in[((size_t)(b*Cin + ci0 + ci)*Hin + iy)*Win + ix];
            ra[v] = val;
            rb[v] = wt[((size_t)tap*Cin + ci0 + ci)*Cout + co0 + pix];
        }
    };
    auto storec = [&](int buf) {
#pragma unroll
        for (int v = 0; v < 8; v++) {
            int idx = tid + v*256;
            int ci = idx >> 7, pix = idx & 127;
            sA[buf][ci*128 + pix] = ra[v];
            sB[buf][ci*128 + pix] = rb[v];
        }
    };

    loadc(0); storec(0); __syncthreads();
    for (int q = 0; q < NCH; q++) {
        if (q + 1 < NCH) loadc(q + 1);
        const float* pA = sA[q & 1];
        const float* pB = sB[q & 1];
#pragma unroll
        for (int kk = 0; kk < 16; kk++) {
            float4 a0 = *(const float4*)&pA[kk*128 + tx*8];
            float4 a1 = *(const float4*)&pA[kk*128 + tx*8 + 4];
            float4 b0 = *(const float4*)&pB[kk*128 + ty*8];
            float4 b1 = *(const float4*)&pB[kk*128 + ty*8 + 4];
            float av[8] = {a0.x,a0.y,a0.z,a0.w,a1.x,a1.y,a1.z,a1.w};
            float bv[8] = {b0.x,b0.y,b0.z,b0.w,b1.x,b1.y,b1.z,b1.w};
#pragma unroll
            for (int i = 0; i < 8; i++)
#pragma unroll
                for (int j = 0; j < 8; j++) acc[i][j] += av[i]*bv[j];
        }
        if (q + 1 < NCH) storec((q + 1) & 1);
        __syncthreads();
    }

    const int yr = y0 + (tx >> 3);
    const int xc = (tx*8) & 63;
#pragma unroll
    for (int j = 0; j < 8; j++) {
        int co = co0 + ty*8 + j;
        float bv = bias[co];
        float4 v0, v1;
        v0.x = acc[0][j]+bv; v0.y = acc[1][j]+bv; v0.z = acc[2][j]+bv; v0.w = acc[3][j]+bv;
        v1.x = acc[4][j]+bv; v1.y = acc[5][j]+bv; v1.z = acc[6][j]+bv; v1.w = acc[7][j]+bv;
        if (relu) {
            v0.x = fmaxf(v0.x,0.f); v0.y = fmaxf(v0.y,0.f); v0.z = fmaxf(v0.z,0.f); v0.w = fmaxf(v0.w,0.f);
            v1.x = fmaxf(v1.x,0.f); v1.y = fmaxf(v1.y,0.f); v1.z = fmaxf(v1.z,0.f); v1.w = fmaxf(v1.w,0.f);
        }
        float* p = out + ((size_t)(b*Cout + co)*4096 + yr*64 + xc);
        *(float4*)p = v0;
        *(float4*)(p + 4) = v1;
    }
}

// ---------------------------------------------------------------------------
// Implicit-GEMM FFMA convT (k4 s2 p1), parity-decomposed, Cout=64, relu.
// Coalesced parity stores (mx = tx + 32*i).
// ---------------------------------------------------------------------------
__global__ __launch_bounds__(256, 2)
void convT_ffma(const float* __restrict__ in, const float* __restrict__ wtT,
                const float* __restrict__ bias, float* __restrict__ out,
                int Cin, int Hin, int Win, int wsh, int hwsh)
{
    __shared__ float sA[2][16*256];
    __shared__ float sB[2][16*64];
    const int tid = threadIdx.x;
    const int tx = tid & 31;
    const int ty = tid >> 5;
    const int P0 = blockIdx.x << 8;
    const int b   = P0 >> hwsh;
    const int lp  = P0 & ((1 << hwsh) - 1);
    const int my0 = lp >> wsh;
    const int p  = blockIdx.z;
    const int ey = p >> 1, ex = p & 1;
    const float* wtp = wtT + (size_t)p*4*Cin*64;
    const int Wo  = Win*2;
    const int HWo = (Hin*Win)*4;
    const int cpt = Cin >> 4;
    const int NCH = 4*cpt;

    float acc[8][8];
#pragma unroll
    for (int i = 0; i < 8; i++)
#pragma unroll
        for (int j = 0; j < 8; j++) acc[i][j] = 0.f;

    float ra[16], rb[4];

    auto loadc = [&](int q) {
        int t = q / cpt;
        int ci0 = (q - t*cpt) << 4;
        int jy = t >> 1, jx = t & 1;
        int ry = (ey == 0) ? (jy == 0 ? 0 : -1) : (jy == 0 ? 1 : 0);
        int rx = (ex == 0) ? (jx == 0 ? 0 : -1) : (jx == 0 ? 1 : 0);
#pragma unroll
        for (int v = 0; v < 16; v++) {
            int idx = tid + v*256;
            int ci = idx >> 8, pix = idx & 255;
            int iy = my0 + (pix >> wsh) + ry;
            int ix = (pix & (Win-1)) + rx;
            float val = 0.f;
            if ((unsigned)iy < (unsigned)Hin && (unsigned)ix < (unsigned)Win)
                val = in[((size_t)(b*Cin + ci0 + ci)*Hin + iy)*Win + ix];
            ra[v] = val;
        }
#pragma unroll
        for (int v = 0; v < 4; v++) {
            int idx = tid + v*256;
            int ci = idx >> 6, n = idx & 63;
            rb[v] = wtp[((size_t)t*Cin + ci0 + ci)*64 + n];
        }
    };
    auto storec = [&](int buf) {
#pragma unroll
        for (int v = 0; v < 16; v++) {
            int idx = tid + v*256;
            int ci = idx >> 8, pix = idx & 255;
            sA[buf][ci*256 + pix] = ra[v];
        }
#pragma unroll
        for (int v = 0; v < 4; v++) {
            int idx = tid + v*256;
            int ci = idx >> 6, n = idx & 63;
            sB[buf][ci*64 + n] = rb[v];
        }
    };

    loadc(0); storec(0); __syncthreads();
    for (int q = 0; q < NCH; q++) {
        if (q + 1 < NCH) loadc(q + 1);
        const float* pA = sA[q & 1];
        const float* pB = sB[q & 1];
#pragma unroll
        for (int kk = 0; kk < 16; kk++) {
            float av[8];
#pragma unroll
            for (int i = 0; i < 8; i++)
                av[i] = pA[kk*256 + tx + 32*i];
            float4 b0 = *(const float4*)&pB[kk*64 + ty*8];
            float4 b1 = *(const float4*)&pB[kk*64 + ty*8 + 4];
            float bv[8] = {b0.x,b0.y,b0.z,b0.w,b1.x,b1.y,b1.z,b1.w};
#pragma unroll
            for (int i = 0; i < 8; i++)
#pragma unroll
                for (int j = 0; j < 8; j++) acc[i][j] += av[i]*bv[j];
        }
        if (q + 1 < NCH) storec((q + 1) & 1);
        __syncthreads();
    }

#pragma unroll
    for (int j = 0; j < 8; j++) {
        int co = ty*8 + j;
        float bv = bias[co];
        float* pb = out + (size_t)(b*64 + co)*HWo + ex;
#pragma unroll
        for (int i = 0; i < 8; i++) {
            int gp = lp + tx + 32*i;
            int my = gp >> wsh;
            int mx = gp & (Win-1);
            int oy = 2*my + ey;
            pb[oy*Wo + 2*mx] = fmaxf(acc[i][j] + bv, 0.f);
        }
    }
}

// ---------------------------------------------------------------------------
// convT4 (k4 s2 p1, Cin=64 -> Cout=3, tanh): per-parity 4-tap form.
// Weights wp[ci][pt(16)][co pad 4]. Dynamic smem 54784 B.
// ---------------------------------------------------------------------------
__global__ __launch_bounds__(256)
void convT4_ffma(const float* __restrict__ in, const float* __restrict__ wp,
                 const float* __restrict__ bias, float* __restrict__ out)
{
    extern __shared__ float dynf[];
    float* sA = dynf;              // [16 ci][3 rows][264]
    float* sB = dynf + 16*792;     // [16 ci][16 pt][4]

    const int tid = threadIdx.x;
    const int b  = blockIdx.x >> 8;
    const int my = blockIdx.x & 255;
    const float* inb = in + (size_t)b*64*65536;

    float acc[12];
#pragma unroll
    for (int i = 0; i < 12; i++) acc[i] = 0.f;

    for (int ci0 = 0; ci0 < 64; ci0 += 16) {
        for (int idx = tid; idx < 16*3*258; idx += 256) {
            int ci = idx / 774;
            int rem = idx - ci*774;
            int r = rem / 258, c = rem - r*258;
            int iy = my - 1 + r, ix = c - 1;
            float v = 0.f;
            if ((unsigned)iy < 256u && (unsigned)ix < 256u)
                v = inb[((size_t)(ci0 + ci)*256 + iy)*256 + ix];
            sA[ci*792 + r*264 + c] = v;
        }
        for (int idx = tid; idx < 1024; idx += 256)
            sB[idx] = wp[ci0*64 + idx];
        __syncthreads();

        for (int ci = 0; ci < 16; ci++) {
            float n[9];
#pragma unroll
            for (int r = 0; r < 3; r++)
#pragma unroll
                for (int c = 0; c < 3; c++)
                    n[r*3 + c] = sA[ci*792 + r*264 + c + tid];
#pragma unroll
            for (int pt = 0; pt < 16; pt++) {
                const int p = pt >> 2, t = pt & 3;
                const int ey = p >> 1, ex = p & 1;
                const int jy = t >> 1, jx = t & 1;
                const int ry = (ey == 0) ? (jy == 0 ? 0 : -1) : (jy == 0 ? 1 : 0);
                const int rx = (ex == 0) ? (jx == 0 ? 0 : -1) : (jx == 0 ? 1 : 0);
                const int ni = (1 + ry)*3 + (1 + rx);
                float a = n[ni];
                const float4 w = *(const float4*)&sB[ci*64 + pt*4];
                acc[p*3 + 0] += a*w.x;
                acc[p*3 + 1] += a*w.y;
                acc[p*3 + 2] += a*w.z;
            }
        }
        __syncthreads();
    }

    const int mx = tid;
#pragma unroll
    for (int p = 0; p < 4; p++) {
        int ey = p >> 1, ex = p & 1;
        int oy = 2*my + ey;
#pragma unroll
        for (int co = 0; co < 3; co++) {
            float v = tanhf(acc[p*3 + co] + bias[co]);
            out[(((size_t)b*3 + co)*512 + oy)*512 + 2*mx + ex] = v;
        }
    }
}

// ---------------------------------------------------------------------------
// Fused weight repack (single launch)
// ---------------------------------------------------------------------------
__device__ __forceinline__ void rp_conv(const float* w, float* wt,
                                        int Cin, int Cout, int KK, int idx)
{
    int co = idx % Cout; int r = idx / Cout;
    int ci = r % Cin;    int tap = r / Cin;
    wt[idx] = w[(co*Cin + ci)*KK + tap];
}

__device__ __forceinline__ void rp_convT(const float* w, float* wtT,
                                         int Cin, int Cout, int idx)
{
    int co = idx % Cout; int r = idx / Cout;
    int ci = r % Cin;    int pt = r / Cin;
    int p = pt >> 2, t = pt & 3;
    int ey = p >> 1, ex = p & 1;
    int jy = t >> 1, jx = t & 1;
    int ky = (ey == 0) ? (jy == 0 ? 1 : 3) : (jy == 0 ? 0 : 2);
    int kx = (ex == 0) ? (jx == 0 ? 1 : 3) : (jx == 0 ? 0 : 2);
    wtT[idx] = w[((ci*Cout + co)*4 + ky)*4 + kx];
}

// dec_w4 (ci=64, co=3, 4, 4) -> wp[ci][pt(16)][co pad 4]
__device__ __forceinline__ void rp_w4(const float* w, float* wp, int idx)
{
    int ci = idx >> 6;
    int rem = idx & 63;
    int pt = rem >> 2, c = rem & 3;
    float v = 0.f;
    if (c < 3) {
        int p = pt >> 2, t = pt & 3;
        int ey = p >> 1, ex = p & 1;
        int jy = t >> 1, jx = t & 1;
        int ky = (ey == 0) ? (jy == 0 ? 1 : 3) : (jy == 0 ? 0 : 2);
        int kx = (ex == 0) ? (jx == 0 ? 1 : 3) : (jx == 0 ? 0 : 2);
        v = w[((ci*3 + c)*4 + ky)*4 + kx];
    }
    wp[idx] = v;
}

__global__ void repack_all(const float* ew1, const float* ew2, const float* ew3,
                           const float* ew4, const float* dw1, const float* dw2,
                           const float* dw3, const float* dw4,
                           float* wt_e1, float* wt_e2, float* wt_e3, float* wt_e4,
                           float* wt_d1, float* wtT_d2, float* wtT_d3, float* w4p)
{
    int idx = blockIdx.x*256 + threadIdx.x;
    if (idx < 3072)   { rp_conv(ew1, wt_e1, 3, 64, 16, idx); return; }
    idx -= 3072;
    if (idx < 131072) { rp_conv(ew2, wt_e2, 64, 128, 16, idx); return; }
    idx -= 131072;
    if (idx < 294912) { rp_conv(ew3, wt_e3, 128, 256, 9, idx); return; }
    idx -= 294912;
    if (idx < 589824) { rp_conv(ew4, wt_e4, 256, 256, 9, idx); return; }
    idx -= 589824;
    if (idx < 294912) { rp_conv(dw1, wt_d1, 256, 128, 9, idx); return; }
    idx -= 294912;
    if (idx < 131072) { rp_convT(dw2, wtT_d2, 128, 64, idx); return; }
    idx -= 131072;
    if (idx < 65536)  { rp_convT(dw3, wtT_d3, 64, 64, idx); return; }
    idx -= 65536;
    if (idx < 4096)   { rp_w4(dw4, w4p, idx); }
}

// ---------------------------------------------------------------------------
// Helpers
// ---------------------------------------------------------------------------
__global__ void cnorm_kernel(const float* __restrict__ cb, float* __restrict__ cn) {
    int row  = (blockIdx.x*blockDim.x + threadIdx.x) >> 5;
    int lane = threadIdx.x & 31;
    if (row >= 4096) return;
    const float* p = cb + (size_t)row*256;
    float s = 0.f;
    for (int c = lane; c < 256; c += 32) { float v = p[c]; s += v*v; }
#pragma unroll
    for (int o = 16; o; o >>= 1) s += __shfl_down_sync(0xffffffffu, s, o);
    if (!lane) cn[row] = s;
}

__global__ void zero_loss(double* l) { if (threadIdx.x < 4) l[threadIdx.x] = 0.0; }

__global__ void write_loss(const double* __restrict__ l, float* __restrict__ o) {
    if (threadIdx.x < 4)
        o[threadIdx.x] = (float)(l[threadIdx.x] * (1.0/(65536.0*256.0)));
}

__global__ void z_to_tokens(const float* __restrict__ z,
                            float* __restrict__ resid, float* __restrict__ qsum)
{
    __shared__ float t[32][33];
    int b  = blockIdx.z;
    int s0 = blockIdx.x*32;
    int c0 = blockIdx.y*32;
    int x  = threadIdx.x;
    for (int y = threadIdx.y; y < 32; y += 8)
        t[y][x] = z[((size_t)b*256 + c0 + y)*4096 + s0 + x];
    __syncthreads();
    for (int y = threadIdx.y; y < 32; y += 8) {
        size_t o = ((size_t)b*4096 + s0 + y)*256 + c0 + x;
        resid[o] = t[x][y];
        qsum[o]  = 0.f;
    }
}

__global__ void tokens_to_z(const float* __restrict__ qsum,
                            float* __restrict__ z1, float* __restrict__ z2)
{
    __shared__ float t[32][33];
    int b  = blockIdx.z;
    int c0 = blockIdx.x*32;
    int s0 = blockIdx.y*32;
    int x  = threadIdx.x;
    for (int y = threadIdx.y; y < 32; y += 8)
        t[y][x] = qsum[((size_t)b*4096 + s0 + y)*256 + c0 + x];
    __syncthreads();
    for (int y = threadIdx.y; y < 32; y += 8) {
        float v = t[x][y];
        size_t o = ((size_t)b*256 + c0 + y)*4096 + s0 + x;
        z1[o] = v; z2[o] = v;
    }
}

// ---------------------------------------------------------------------------
// Launch
// ---------------------------------------------------------------------------
extern "C" void kernel_launch(void* const* d_in, const int* in_sizes, int n_in,
                              void* d_out, int out_size)
{
    const float* x   = (const float*)d_in[0];
    const float* ew1 = (const float*)d_in[1];  const float* eb1 = (const float*)d_in[2];
    const float* ew2 = (const float*)d_in[3];  const float* eb2 = (const float*)d_in[4];
    const float* ew3 = (const float*)d_in[5];  const float* eb3 = (const float*)d_in[6];
    const float* ew4 = (const float*)d_in[7];  const float* eb4 = (const float*)d_in[8];
    const float* cbs = (const float*)d_in[9];
    const float* dw1 = (const float*)d_in[10]; const float* db1 = (const float*)d_in[11];
    const float* dw2 = (const float*)d_in[12]; const float* db2 = (const float*)d_in[13];
    const float* dw3 = (const float*)d_in[14]; const float* db3 = (const float*)d_in[15];
    const float* dw4 = (const float*)d_in[16]; const float* db4 = (const float*)d_in[17];
    float* out = (float*)d_out;

    float *h1, *h2, *h3, *z, *resid, *qsum, *cnorm, *w4p, *wt, *wtT, *d3;
    double* loss; unsigned* rowmin; int *cand, *ccnt;
    cudaGetSymbolAddress((void**)&h1,    g_h1);
    cudaGetSymbolAddress((void**)&h2,    g_h2);
    cudaGetSymbolAddress((void**)&h3,    g_h3);
    cudaGetSymbolAddress((void**)&z,     g_z);
    cudaGetSymbolAddress((void**)&resid, g_resid);
    cudaGetSymbolAddress((void**)&qsum,  g_qsum);
    cudaGetSymbolAddress((void**)&loss,  g_loss);
    cudaGetSymbolAddress((void**)&cnorm, g_cnorm);
    cudaGetSymbolAddress((void**)&rowmin,g_rowmin);
    cudaGetSymbolAddress((void**)&cand,  g_cand);
    cudaGetSymbolAddress((void**)&ccnt,  g_ccnt);
    cudaGetSymbolAddress((void**)&w4p,   g_w4p);
    cudaGetSymbolAddress((void**)&wt,    g_wt);
    cudaGetSymbolAddress((void**)&wtT,   g_wtT);
    cudaGetSymbolAddress((void**)&d3,    g_d3);

    float* wt_e1  = wt;                               // 16*3*64    = 3072
    float* wt_e2  = wt + 3072;                        // 16*64*128  = 131072
    float* wt_e3  = wt_e2 + 131072;                   // 9*128*256  = 294912
    float* wt_e4  = wt_e3 + 294912;                   // 9*256*256  = 589824
    float* wt_d1  = wt_e4 + 589824;                   // 9*256*128  = 294912
    float* wtT_d2 = wtT;                              // 16*128*64  = 131072
    float* wtT_d3 = wtT + 131072;                     // 16*64*64   = 65536

    // output layout: recon | indices | commit_loss | quantized
    float* recO   = out;
    float* idxO   = out + 12582912;
    float* lossO  = idxO + 262144;
    float* quantO = lossO + 4;

    const int PA_SMEM  = 2*PLW*4 + 512;               // 34304
    const int CT4_SMEM = (16*792 + 1024)*4;           // 54784
    cudaFuncSetAttribute(vq_gemm_approx, cudaFuncAttributeMaxDynamicSharedMemorySize, PA_SMEM);
    cudaFuncSetAttribute(convT4_ffma,    cudaFuncAttributeMaxDynamicSharedMemorySize, CT4_SMEM);

    // prep
    repack_all  <<<5916, 256>>>(ew1, ew2, ew3, ew4, dw1, dw2, dw3, dw4,
                                wt_e1, wt_e2, wt_e3, wt_e4, wt_d1,
                                wtT_d2, wtT_d3, w4p);
    cnorm_kernel<<<512, 256>>>(cbs, cnorm);
    zero_loss   <<<1, 32>>>(loss);
    init_vq     <<<256, 1024>>>(rowmin, ccnt);

    // ---- encoder (exact fp32) ----
    conv1_ffma<<<2048, 256>>>(x, wt_e1, eb1, h1);
    conv_ffma<4,2><<<dim3(512, 1), 256>>>(h1, wt_e2, eb2, h2,  64, 128, 128, 128, 1);
    conv_ffma<3,1><<<dim3(512, 2), 256>>>(h2, wt_e3, eb3, h3, 128,  64,  64, 256, 1);
    conv_ffma<3,1><<<dim3(512, 2), 256>>>(h3, wt_e4, eb4, z,  256,  64,  64, 256, 0);

    // ---- residual VQ: tf32 approx distances + candidate lists + exact rescore ----
    z_to_tokens<<<dim3(128, 8, 16), dim3(32, 8)>>>(z, resid, qsum);
    __nv_bfloat16* Dh = (__nv_bfloat16*)d3;
    for (int s = 0; s < 4; s++) {
        vq_gemm_approx  <<<dim3(512, 8), 256, PA_SMEM>>>(resid, cbs + (size_t)s*1024*256,
                                                         cnorm + s*1024, Dh,
                                                         rowmin + s*65536, cand,
                                                         ccnt + s*65536);
        vq_select_update<<<8192, 256>>>(Dh, cbs + (size_t)s*1024*256, cnorm + s*1024,
                                        rowmin + s*65536, cand, ccnt + s*65536,
                                        resid, qsum, idxO, s, loss);
    }
    write_loss <<<1, 32>>>(loss, lossO);
    tokens_to_z<<<dim3(8, 128, 16), dim3(32, 8)>>>(qsum, z, quantO);

    // ---- decoder (FFMA, exact) ----
    conv_ffma<3,1><<<dim3(512, 1), 256>>>(z, wt_d1, db1, h2, 256, 64, 64, 128, 1);
    convT_ffma<<<dim3( 256, 1, 4), 256>>>(h2, wtT_d2, db2, h1, 128,  64,  64, 6, 12);
    convT_ffma<<<dim3(1024, 1, 4), 256>>>(h1, wtT_d3, db3, d3,  64, 128, 128, 7, 14);
    convT4_ffma<<<4096, 256, CT4_SMEM>>>(d3, w4p, db4, recO);
}

// round 16
// speedup vs baseline: 1.0206x; 1.0206x over previous
#include <cuda_runtime.h>
#include <cuda_bf16.h>
#include <cstdint>

// ---------------------------------------------------------------------------
// Scratch (device globals — no allocation allowed)
// ---------------------------------------------------------------------------
__device__ float g_h1[16*64*128*128];          // enc1 out / dec2 out (reused)
__device__ float g_h2[16*128*64*64];           // enc2 out / dec1 out (reused)
__device__ float g_h3[16*256*64*64];           // enc3 out
__device__ float g_z [16*256*64*64];           // enc4 out (z) / quantized NCHW (reused)
__device__ float g_resid[65536*256];
__device__ float g_qsum [65536*256];
__device__ double g_loss[4];
__device__ float g_cnorm[4*1024];
__device__ unsigned g_rowmin[4*65536];
__device__ float g_w4p[64*16*4];               // dec_w4 repacked [ci][pt(16)][co pad 4]
__device__ float g_wt[1313792];                // conv weights repacked [tap][ci][co]
__device__ float g_wtT[196608];                // convT weights [parity][tap][ci][co]
__device__ float g_d3[16*64*256*256];          // dec3 out; ALSO the 65536x1024 D (bf16)

// ---------------------------------------------------------------------------
// packed f32x2 helpers (two independent IEEE fp32 FMAs -> bit-exact)
// ---------------------------------------------------------------------------
__device__ __forceinline__ uint64_t pack2(float lo, float hi) {
    uint64_t r;
    asm("mov.b64 %0, {%1, %2};" : "=l"(r) : "f"(lo), "f"(hi));
    return r;
}
__device__ __forceinline__ float2 unpack2(uint64_t v) {
    float lo, hi;
    asm("mov.b64 {%0, %1}, %2;" : "=f"(lo), "=f"(hi) : "l"(v));
    return make_float2(lo, hi);
}
__device__ __forceinline__ void ffma2(uint64_t& c, uint64_t a, uint64_t b) {
    asm("fma.rn.f32x2 %0, %1, %2, %0;" : "+l"(c) : "l"(a), "l"(b));
}

// ---------------------------------------------------------------------------
// tf32 helpers (approximate Phase-A path only; correctness never depends on it)
// ---------------------------------------------------------------------------
__device__ __forceinline__ uint32_t f2tf(float f) {
    uint32_t u;
    asm("cvt.rna.tf32.f32 %0, %1;" : "=r"(u) : "f"(f));
    return u;
}

__device__ __forceinline__ void mma_tf32(float* c, const uint32_t* a,
                                         uint32_t b0, uint32_t b1) {
    asm volatile(
        "mma.sync.aligned.m16n8k8.row.col.f32.tf32.tf32.f32 "
        "{%0,%1,%2,%3},{%4,%5,%6,%7},{%8,%9},{%0,%1,%2,%3};"
        : "+f"(c[0]), "+f"(c[1]), "+f"(c[2]), "+f"(c[3])
        : "r"(a[0]), "r"(a[1]), "r"(a[2]), "r"(a[3]), "r"(b0), "r"(b1));
}

// order-preserving float <-> uint32 (for atomicMin)
__device__ __forceinline__ unsigned fenc(float d) {
    unsigned u = __float_as_uint(d);
    return (u & 0x80000000u) ? ~u : (u | 0x80000000u);
}
__device__ __forceinline__ float fdec(unsigned e) {
    unsigned u = (e & 0x80000000u) ? (e & 0x7FFFFFFFu) : ~e;
    return __uint_as_float(u);
}

static const int PLW = 128*33;   // one smem plane in words (stride 33: conflict-free)

// ---------------------------------------------------------------------------
// Phase A: approximate distance matrix, single tf32 MMA, D stored as bf16.
// D[m,n] = cn[n] - 2 * R[m,:].cb[n,:]; per-row min -> rowmin (atomicMin).
// ---------------------------------------------------------------------------
__global__ __launch_bounds__(256)
void vq_gemm_approx(const float* __restrict__ R, const float* __restrict__ cb,
                    const float* __restrict__ cn, __nv_bfloat16* __restrict__ D,
                    unsigned* __restrict__ rowmin)
{
    extern __shared__ uint32_t dyn[];
    uint32_t* sA = dyn;
    uint32_t* sB = dyn + PLW;
    unsigned* sMin = (unsigned*)(dyn + 2*PLW);

    const int tid  = threadIdx.x;
    const int lane = tid & 31;
    const int warp = tid >> 5;
    const int wm = warp & 1;
    const int wn = warp >> 1;
    const int m0 = blockIdx.x << 7;
    const int n0 = blockIdx.y << 7;

    float acc[4][4][4];
#pragma unroll
    for (int i = 0; i < 4; i++)
#pragma unroll
        for (int j = 0; j < 4; j++)
#pragma unroll
            for (int k = 0; k < 4; k++) acc[i][j][k] = 0.f;

    if (tid < 128) sMin[tid] = 0xFFFFFFFFu;

    for (int k0 = 0; k0 < 256; k0 += 32) {
#pragma unroll
        for (int i = 0; i < 4; i++) {
            int idx4 = tid + i*256;
            int m  = idx4 >> 3;
            int kq = idx4 & 7;
            int oa = m*33 + kq*4;
            float4 a = *(const float4*)(R  + (size_t)(m0 + m)*256 + k0 + kq*4);
            sA[oa+0] = f2tf(a.x); sA[oa+1] = f2tf(a.y);
            sA[oa+2] = f2tf(a.z); sA[oa+3] = f2tf(a.w);
            float4 b = *(const float4*)(cb + (size_t)(n0 + m)*256 + k0 + kq*4);
            sB[oa+0] = f2tf(b.x); sB[oa+1] = f2tf(b.y);
            sB[oa+2] = f2tf(b.z); sB[oa+3] = f2tf(b.w);
        }
        __syncthreads();

#pragma unroll
        for (int ks = 0; ks < 4; ks++) {
            const int kb = ks*8 + (lane & 3);
            uint32_t bf[4][2];
#pragma unroll
            for (int fn = 0; fn < 4; fn++) {
                int n = wn*32 + fn*8 + (lane >> 2);
                bf[fn][0] = sB[n*33 + kb];  bf[fn][1] = sB[n*33 + kb + 4];
            }
#pragma unroll
            for (int fm = 0; fm < 4; fm++) {
                int r = wm*64 + fm*16 + (lane >> 2);
                uint32_t af[4];
                af[0] = sA[r*33 + kb];     af[1] = sA[(r+8)*33 + kb];
                af[2] = sA[r*33 + kb+4];   af[3] = sA[(r+8)*33 + kb+4];
#pragma unroll
                for (int fn = 0; fn < 4; fn++)
                    mma_tf32(acc[fm][fn], af, bf[fn][0], bf[fn][1]);
            }
        }
        __syncthreads();
    }

    float cnv[4][2];
#pragma unroll
    for (int fn = 0; fn < 4; fn++) {
        int col = n0 + wn*32 + fn*8 + 2*(lane & 3);
        cnv[fn][0] = cn[col];
        cnv[fn][1] = cn[col + 1];
    }
#pragma unroll
    for (int fm = 0; fm < 4; fm++) {
#pragma unroll
        for (int h = 0; h < 2; h++) {
            int rl = wm*64 + fm*16 + (lane >> 2) + h*8;
            int rg = m0 + rl;
            float mn = 3.402823466e38f;
#pragma unroll
            for (int fn = 0; fn < 4; fn++) {
                int col = n0 + wn*32 + fn*8 + 2*(lane & 3);
                float vx = cnv[fn][0] - 2.f*acc[fm][fn][h*2 + 0];
                float vy = cnv[fn][1] - 2.f*acc[fm][fn][h*2 + 1];
                mn = fminf(mn, fminf(vx, vy));
                *(__nv_bfloat162*)(D + (size_t)rg*1024 + col) =
                    __floats2bfloat162_rn(vx, vy);
            }
            atomicMin(&sMin[rl], fenc(mn));
        }
    }
    __syncthreads();
    if (tid < 128) atomicMin(&rowmin[m0 + tid], sMin[tid]);
}

__global__ void init_rowmin_all(unsigned* rowmin) {
    rowmin[blockIdx.x*1024 + threadIdx.x] = 0xFFFFFFFFu;
}

// ---------------------------------------------------------------------------
// Phase B: one warp per token; batched bf16x2 scan (4 loads in flight),
// exact-FFMA rescore of candidates within EPS of the approx row-min,
// order-independent lowest-index tie-break, fused vq_update.
// ---------------------------------------------------------------------------
__global__ __launch_bounds__(256)
void vq_select_update(const __nv_bfloat16* __restrict__ D, const float* __restrict__ cb,
                      const float* __restrict__ cn,
                      const unsigned* __restrict__ rowmin,
                      float* __restrict__ resid, float* __restrict__ qsum,
                      float* __restrict__ idx_out, int stage,
                      double* __restrict__ lossAcc)
{
    __shared__ double sLoss[8];
    const int warp = threadIdx.x >> 5;
    const int lane = threadIdx.x & 31;
    const int t = blockIdx.x*8 + warp;

    const __nv_bfloat16* drow = D + (size_t)t*1024;
    const float thr = fdec(rowmin[t]) + 0.03f;

    float4 r0 = *(const float4*)(resid + (size_t)t*256 + lane*8);
    float4 r1 = *(const float4*)(resid + (size_t)t*256 + lane*8 + 4);

    float bestd = 3.402823466e38f;
    int   bestn = 0x7FFFFFFF;

    auto rescore = [&](int j) {
        const float* c = cb + (size_t)j*256;
        float4 c0 = *(const float4*)(c + lane*8);
        float4 c1 = *(const float4*)(c + lane*8 + 4);
        float dot = r0.x*c0.x + r0.y*c0.y + r0.z*c0.z + r0.w*c0.w
                  + r1.x*c1.x + r1.y*c1.y + r1.z*c1.z + r1.w*c1.w;
#pragma unroll
        for (int o = 16; o; o >>= 1)
            dot += __shfl_xor_sync(0xffffffffu, dot, o);
        float de = cn[j] - 2.f*dot;
        if (de < bestd || (de == bestd && j < bestn)) { bestd = de; bestn = j; }
    };

#pragma unroll
    for (int j0 = 0; j0 < 1024; j0 += 256) {
        float2 dd[4];
#pragma unroll
        for (int u = 0; u < 4; u++) {
            __nv_bfloat162 dv2 =
                *(const __nv_bfloat162*)(drow + j0 + u*64 + lane*2);
            dd[u] = __bfloat1622float2(dv2);
        }
#pragma unroll
        for (int u = 0; u < 4; u++) {
            unsigned me = __ballot_sync(0xffffffffu, dd[u].x <= thr);
            unsigned mo = __ballot_sync(0xffffffffu, dd[u].y <= thr);
            while (me) { int s = __ffs(me) - 1; me &= me - 1; rescore(j0 + u*64 + 2*s); }
            while (mo) { int s = __ffs(mo) - 1; mo &= mo - 1; rescore(j0 + u*64 + 2*s + 1); }
        }
    }

    const float* q = cb + (size_t)bestn*256;
    float4 q0 = *(const float4*)(q + lane*8);
    float4 q1 = *(const float4*)(q + lane*8 + 4);
    float4 s0 = *(float4*)(qsum + (size_t)t*256 + lane*8);
    float4 s1 = *(float4*)(qsum + (size_t)t*256 + lane*8 + 4);

    float ls = 0.f;
    {
        float d;
        d = q0.x-r0.x; ls += d*d;  d = q0.y-r0.y; ls += d*d;
        d = q0.z-r0.z; ls += d*d;  d = q0.w-r0.w; ls += d*d;
        d = q1.x-r1.x; ls += d*d;  d = q1.y-r1.y; ls += d*d;
        d = q1.z-r1.z; ls += d*d;  d = q1.w-r1.w; ls += d*d;
    }
    s0.x += q0.x; s0.y += q0.y; s0.z += q0.z; s0.w += q0.w;
    s1.x += q1.x; s1.y += q1.y; s1.z += q1.z; s1.w += q1.w;
    r0.x -= q0.x; r0.y -= q0.y; r0.z -= q0.z; r0.w -= q0.w;
    r1.x -= q1.x; r1.y -= q1.y; r1.z -= q1.z; r1.w -= q1.w;
    *(float4*)(qsum  + (size_t)t*256 + lane*8)     = s0;
    *(float4*)(qsum  + (size_t)t*256 + lane*8 + 4) = s1;
    *(float4*)(resid + (size_t)t*256 + lane*8)     = r0;
    *(float4*)(resid + (size_t)t*256 + lane*8 + 4) = r1;

#pragma unroll
    for (int o = 16; o; o >>= 1) ls += __shfl_down_sync(0xffffffffu, ls, o);
    if (lane == 0) {
        sLoss[warp] = (double)ls;
        idx_out[(t >> 12)*16384 + stage*4096 + (t & 4095)] = (float)bestn;
    }
    __syncthreads();
    if (threadIdx.x == 0) {
        double tot = 0.0;
#pragma unroll
        for (int w = 0; w < 8; w++) tot += sLoss[w];
        atomicAdd(lossAcc + stage, tot);
    }
}

// ---------------------------------------------------------------------------
// enc1 (4x4 s2 p1, Cin=3 -> Cout=64) as implicit GEMM. M=128 px (one output
// row), N=64, K=48 (16 taps x 3 ci), single smem stage. Coalesced stores.
// ---------------------------------------------------------------------------
__global__ __launch_bounds__(256)
void conv1_ffma(const float* __restrict__ in, const float* __restrict__ wt,
                const float* __restrict__ bias, float* __restrict__ out)
{
    __shared__ float sA[48*128];
    __shared__ float sB[48*64];
    const int tid = threadIdx.x;
    const int tx = tid & 31;
    const int ty = tid >> 5;
    const int b  = blockIdx.x >> 7;
    const int yr = blockIdx.x & 127;

    for (int idx = tid; idx < 48*128; idx += 256) {
        int k  = idx >> 7, px = idx & 127;
        int tap = k/3, ci = k - tap*3;
        int kh = tap >> 2, kw = tap & 3;
        int iy = yr*2 + kh - 1;
        int ix = px*2 + kw - 1;
        float v = 0.f;
        if ((unsigned)iy < 256u && (unsigned)ix < 256u)
            v = in[((size_t)(b*3 + ci)*256 + iy)*256 + ix];
        sA[idx] = v;
    }
    for (int idx = tid; idx < 48*64; idx += 256)
        sB[idx] = wt[idx];
    __syncthreads();

    float acc[4][8];
#pragma unroll
    for (int i = 0; i < 4; i++)
#pragma unroll
        for (int j = 0; j < 8; j++) acc[i][j] = 0.f;

#pragma unroll
    for (int kk = 0; kk < 48; kk++) {
        float av[4];
#pragma unroll
        for (int i = 0; i < 4; i++) av[i] = sA[kk*128 + tx + 32*i];
        float4 b0 = *(const float4*)&sB[kk*64 + ty*8];
        float4 b1 = *(const float4*)&sB[kk*64 + ty*8 + 4];
        float bv[8] = {b0.x,b0.y,b0.z,b0.w,b1.x,b1.y,b1.z,b1.w};
#pragma unroll
        for (int i = 0; i < 4; i++)
#pragma unroll
            for (int j = 0; j < 8; j++) acc[i][j] += av[i]*bv[j];
    }

#pragma unroll
    for (int j = 0; j < 8; j++) {
        int co = ty*8 + j;
        float bv = bias[co];
        float* p = out + ((size_t)(b*64 + co)*128 + yr)*128;
#pragma unroll
        for (int i = 0; i < 4; i++)
            p[tx + 32*i] = fmaxf(acc[i][j] + bv, 0.f);
    }
}

// ---------------------------------------------------------------------------
// Implicit-GEMM conv (3x3 s1 or 4x4 s2, pad 1) using packed fma.rn.f32x2
// (bit-exact vs scalar FFMA: same per-element accumulation order).
// Double-buffered smem, register-staged prefetch, single sync per chunk.
// ---------------------------------------------------------------------------
template<int KSZ, int S>
__global__ __launch_bounds__(256, 2)
void conv_ffma(const float* __restrict__ in, const float* __restrict__ wt,
               const float* __restrict__ bias, float* __restrict__ out,
               int Cin, int Hin, int Win, int Cout, int relu)
{
    __shared__ float sA[2][16*128];
    __shared__ float sB[2][16*128];
    const int tid = threadIdx.x;
    const int tx = tid & 15;
    const int ty = tid >> 4;
    const int m0  = blockIdx.x << 7;
    const int co0 = blockIdx.y << 7;
    const int b   = m0 >> 12;
    const int y0  = (m0 & 4095) >> 6;
    const int cpt = Cin >> 4;
    const int NCH = KSZ*KSZ*cpt;

    uint64_t acc2[8][4];
#pragma unroll
    for (int i = 0; i < 8; i++)
#pragma unroll
        for (int j = 0; j < 4; j++) acc2[i][j] = 0ull;

    float ra[8], rb[8];

    auto loadc = [&](int q) {
        int tap = q / cpt;
        int ci0 = (q - tap*cpt) << 4;
        int dy = tap/KSZ - 1, dx = tap%KSZ - 1;
#pragma unroll
        for (int v = 0; v < 8; v++) {
            int idx = tid + v*256;
            int ci = idx >> 7, pix = idx & 127;
            int iy = (y0 + (pix >> 6))*S + dy;
            int ix = (pix & 63)*S + dx;
            float val = 0.f;
            if ((unsigned)iy < (unsigned)Hin && (unsigned)ix < (unsigned)Win)
                val = in[((size_t)(b*Cin + ci0 + ci)*Hin + iy)*Win + ix];
            ra[v] = val;
            rb[v] = wt[((size_t)tap*Cin + ci0 + ci)*Cout + co0 + pix];
        }
    };
    auto storec = [&](int buf) {
#pragma unroll
        for (int v = 0; v < 8; v++) {
            int idx = tid + v*256;
            int ci = idx >> 7, pix = idx & 127;
            sA[buf][ci*128 + pix] = ra[v];
            sB[buf][ci*128 + pix] = rb[v];
        }
    };

    loadc(0); storec(0); __syncthreads();
    for (int q = 0; q < NCH; q++) {
        if (q + 1 < NCH) loadc(q + 1);
        const float* pA = sA[q & 1];
        const float* pB = sB[q & 1];
#pragma unroll
        for (int kk = 0; kk < 16; kk++) {
            float4 a0 = *(const float4*)&pA[kk*128 + tx*8];
            float4 a1 = *(const float4*)&pA[kk*128 + tx*8 + 4];
            float4 b0 = *(const float4*)&pB[kk*128 + ty*8];
            float4 b1 = *(const float4*)&pB[kk*128 + ty*8 + 4];
            uint64_t bp[4] = {pack2(b0.x, b0.y), pack2(b0.z, b0.w),
                              pack2(b1.x, b1.y), pack2(b1.z, b1.w)};
            float av[8] = {a0.x,a0.y,a0.z,a0.w,a1.x,a1.y,a1.z,a1.w};
#pragma unroll
            for (int i = 0; i < 8; i++) {
                uint64_t aa = pack2(av[i], av[i]);
#pragma unroll
                for (int j = 0; j < 4; j++) ffma2(acc2[i][j], aa, bp[j]);
            }
        }
        if (q + 1 < NCH) storec((q + 1) & 1);
        __syncthreads();
    }

    // unpack accumulators
    float acc[8][8];
#pragma unroll
    for (int i = 0; i < 8; i++)
#pragma unroll
        for (int j = 0; j < 4; j++) {
            float2 p = unpack2(acc2[i][j]);
            acc[i][2*j]     = p.x;
            acc[i][2*j + 1] = p.y;
        }

    const int yr = y0 + (tx >> 3);
    const int xc = (tx*8) & 63;
#pragma unroll
    for (int j = 0; j < 8; j++) {
        int co = co0 + ty*8 + j;
        float bv = bias[co];
        float4 v0, v1;
        v0.x = acc[0][j]+bv; v0.y = acc[1][j]+bv; v0.z = acc[2][j]+bv; v0.w = acc[3][j]+bv;
        v1.x = acc[4][j]+bv; v1.y = acc[5][j]+bv; v1.z = acc[6][j]+bv; v1.w = acc[7][j]+bv;
        if (relu) {
            v0.x = fmaxf(v0.x,0.f); v0.y = fmaxf(v0.y,0.f); v0.z = fmaxf(v0.z,0.f); v0.w = fmaxf(v0.w,0.f);
            v1.x = fmaxf(v1.x,0.f); v1.y = fmaxf(v1.y,0.f); v1.z = fmaxf(v1.z,0.f); v1.w = fmaxf(v1.w,0.f);
        }
        float* p = out + ((size_t)(b*Cout + co)*4096 + yr*64 + xc);
        *(float4*)p = v0;
        *(float4*)(p + 4) = v1;
    }
}

// ---------------------------------------------------------------------------
// Implicit-GEMM convT (k4 s2 p1), parity-decomposed, Cout=64, relu,
// packed fma.rn.f32x2 inner loop (bit-exact). Coalesced parity stores.
// ---------------------------------------------------------------------------
__global__ __launch_bounds__(256, 2)
void convT_ffma(const float* __restrict__ in, const float* __restrict__ wtT,
                const float* __restrict__ bias, float* __restrict__ out,
                int Cin, int Hin, int Win, int wsh, int hwsh)
{
    __shared__ float sA[2][16*256];
    __shared__ float sB[2][16*64];
    const int tid = threadIdx.x;
    const int tx = tid & 31;
    const int ty = tid >> 5;
    const int P0 = blockIdx.x << 8;
    const int b   = P0 >> hwsh;
    const int lp  = P0 & ((1 << hwsh) - 1);
    const int my0 = lp >> wsh;
    const int p  = blockIdx.z;
    const int ey = p >> 1, ex = p & 1;
    const float* wtp = wtT + (size_t)p*4*Cin*64;
    const int Wo  = Win*2;
    const int HWo = (Hin*Win)*4;
    const int cpt = Cin >> 4;
    const int NCH = 4*cpt;

    uint64_t acc2[8][4];
#pragma unroll
    for (int i = 0; i < 8; i++)
#pragma unroll
        for (int j = 0; j < 4; j++) acc2[i][j] = 0ull;

    float ra[16], rb[4];

    auto loadc = [&](int q) {
        int t = q / cpt;
        int ci0 = (q - t*cpt) << 4;
        int jy = t >> 1, jx = t & 1;
        int ry = (ey == 0) ? (jy == 0 ? 0 : -1) : (jy == 0 ? 1 : 0);
        int rx = (ex == 0) ? (jx == 0 ? 0 : -1) : (jx == 0 ? 1 : 0);
#pragma unroll
        for (int v = 0; v < 16; v++) {
            int idx = tid + v*256;
            int ci = idx >> 8, pix = idx & 255;
            int iy = my0 + (pix >> wsh) + ry;
            int ix = (pix & (Win-1)) + rx;
            float val = 0.f;
            if ((unsigned)iy < (unsigned)Hin && (unsigned)ix < (unsigned)Win)
                val = in[((size_t)(b*Cin + ci0 + ci)*Hin + iy)*Win + ix];
            ra[v] = val;
        }
#pragma unroll
        for (int v = 0; v < 4; v++) {
            int idx = tid + v*256;
            int ci = idx >> 6, n = idx & 63;
            rb[v] = wtp[((size_t)t*Cin + ci0 + ci)*64 + n];
        }
    };
    auto storec = [&](int buf) {
#pragma unroll
        for (int v = 0; v < 16; v++) {
            int idx = tid + v*256;
            int ci = idx >> 8, pix = idx & 255;
            sA[buf][ci*256 + pix] = ra[v];
        }
#pragma unroll
        for (int v = 0; v < 4; v++) {
            int idx = tid + v*256;
            int ci = idx >> 6, n = idx & 63;
            sB[buf][ci*64 + n] = rb[v];
        }
    };

    loadc(0); storec(0); __syncthreads();
    for (int q = 0; q < NCH; q++) {
        if (q + 1 < NCH) loadc(q + 1);
        const float* pA = sA[q & 1];
        const float* pB = sB[q & 1];
#pragma unroll
        for (int kk = 0; kk < 16; kk++) {
            float4 b0 = *(const float4*)&pB[kk*64 + ty*8];
            float4 b1 = *(const float4*)&pB[kk*64 + ty*8 + 4];
            uint64_t bp[4] = {pack2(b0.x, b0.y), pack2(b0.z, b0.w),
                              pack2(b1.x, b1.y), pack2(b1.z, b1.w)};
#pragma unroll
            for (int i = 0; i < 8; i++) {
                float a = pA[kk*256 + tx + 32*i];
                uint64_t aa = pack2(a, a);
#pragma unroll
                for (int j = 0; j < 4; j++) ffma2(acc2[i][j], aa, bp[j]);
            }
        }
        if (q + 1 < NCH) storec((q + 1) & 1);
        __syncthreads();
    }

    float acc[8][8];
#pragma unroll
    for (int i = 0; i < 8; i++)
#pragma unroll
        for (int j = 0; j < 4; j++) {
            float2 pv = unpack2(acc2[i][j]);
            acc[i][2*j]     = pv.x;
            acc[i][2*j + 1] = pv.y;
        }

#pragma unroll
    for (int j = 0; j < 8; j++) {
        int co = ty*8 + j;
        float bv = bias[co];
        float* pb = out + (size_t)(b*64 + co)*HWo + ex;
#pragma unroll
        for (int i = 0; i < 8; i++) {
            int gp = lp + tx + 32*i;
            int my = gp >> wsh;
            int mx = gp & (Win-1);
            int oy = 2*my + ey;
            pb[oy*Wo + 2*mx] = fmaxf(acc[i][j] + bv, 0.f);
        }
    }
}

// ---------------------------------------------------------------------------
// convT4 (k4 s2 p1, Cin=64 -> Cout=3, tanh): per-parity 4-tap form.
// Weights wp[ci][pt(16)][co pad 4]. Dynamic smem 54784 B.
// ---------------------------------------------------------------------------
__global__ __launch_bounds__(256)
void convT4_ffma(const float* __restrict__ in, const float* __restrict__ wp,
                 const float* __restrict__ bias, float* __restrict__ out)
{
    extern __shared__ float dynf[];
    float* sA = dynf;              // [16 ci][3 rows][264]
    float* sB = dynf + 16*792;     // [16 ci][16 pt][4]

    const int tid = threadIdx.x;
    const int b  = blockIdx.x >> 8;
    const int my = blockIdx.x & 255;
    const float* inb = in + (size_t)b*64*65536;

    float acc[12];
#pragma unroll
    for (int i = 0; i < 12; i++) acc[i] = 0.f;

    for (int ci0 = 0; ci0 < 64; ci0 += 16) {
        for (int idx = tid; idx < 16*3*258; idx += 256) {
            int ci = idx / 774;
            int rem = idx - ci*774;
            int r = rem / 258, c = rem - r*258;
            int iy = my - 1 + r, ix = c - 1;
            float v = 0.f;
            if ((unsigned)iy < 256u && (unsigned)ix < 256u)
                v = inb[((size_t)(ci0 + ci)*256 + iy)*256 + ix];
            sA[ci*792 + r*264 + c] = v;
        }
        for (int idx = tid; idx < 1024; idx += 256)
            sB[idx] = wp[ci0*64 + idx];
        __syncthreads();

        for (int ci = 0; ci < 16; ci++) {
            float n[9];
#pragma unroll
            for (int r = 0; r < 3; r++)
#pragma unroll
                for (int c = 0; c < 3; c++)
                    n[r*3 + c] = sA[ci*792 + r*264 + c + tid];
#pragma unroll
            for (int pt = 0; pt < 16; pt++) {
                const int p = pt >> 2, t = pt & 3;
                const int ey = p >> 1, ex = p & 1;
                const int jy = t >> 1, jx = t & 1;
                const int ry = (ey == 0) ? (jy == 0 ? 0 : -1) : (jy == 0 ? 1 : 0);
                const int rx = (ex == 0) ? (jx == 0 ? 0 : -1) : (jx == 0 ? 1 : 0);
                const int ni = (1 + ry)*3 + (1 + rx);
                float a = n[ni];
                const float4 w = *(const float4*)&sB[ci*64 + pt*4];
                acc[p*3 + 0] += a*w.x;
                acc[p*3 + 1] += a*w.y;
                acc[p*3 + 2] += a*w.z;
            }
        }
        __syncthreads();
    }

    const int mx = tid;
#pragma unroll
    for (int p = 0; p < 4; p++) {
        int ey = p >> 1, ex = p & 1;
        int oy = 2*my + ey;
#pragma unroll
        for (int co = 0; co < 3; co++) {
            float v = tanhf(acc[p*3 + co] + bias[co]);
            out[(((size_t)b*3 + co)*512 + oy)*512 + 2*mx + ex] = v;
        }
    }
}

// ---------------------------------------------------------------------------
// Fused weight repack (single launch)
// ---------------------------------------------------------------------------
__device__ __forceinline__ void rp_conv(const float* w, float* wt,
                                        int Cin, int Cout, int KK, int idx)
{
    int co = idx % Cout; int r = idx / Cout;
    int ci = r % Cin;    int tap = r / Cin;
    wt[idx] = w[(co*Cin + ci)*KK + tap];
}

__device__ __forceinline__ void rp_convT(const float* w, float* wtT,
                                         int Cin, int Cout, int idx)
{
    int co = idx % Cout; int r = idx / Cout;
    int ci = r % Cin;    int pt = r / Cin;
    int p = pt >> 2, t = pt & 3;
    int ey = p >> 1, ex = p & 1;
    int jy = t >> 1, jx = t & 1;
    int ky = (ey == 0) ? (jy == 0 ? 1 : 3) : (jy == 0 ? 0 : 2);
    int kx = (ex == 0) ? (jx == 0 ? 1 : 3) : (jx == 0 ? 0 : 2);
    wtT[idx] = w[((ci*Cout + co)*4 + ky)*4 + kx];
}

// dec_w4 (ci=64, co=3, 4, 4) -> wp[ci][pt(16)][co pad 4]
__device__ __forceinline__ void rp_w4(const float* w, float* wp, int idx)
{
    int ci = idx >> 6;
    int rem = idx & 63;
    int pt = rem >> 2, c = rem & 3;
    float v = 0.f;
    if (c < 3) {
        int p = pt >> 2, t = pt & 3;
        int ey = p >> 1, ex = p & 1;
        int jy = t >> 1, jx = t & 1;
        int ky = (ey == 0) ? (jy == 0 ? 1 : 3) : (jy == 0 ? 0 : 2);
        int kx = (ex == 0) ? (jx == 0 ? 1 : 3) : (jx == 0 ? 0 : 2);
        v = w[((ci*3 + c)*4 + ky)*4 + kx];
    }
    wp[idx] = v;
}

__global__ void repack_all(const float* ew1, const float* ew2, const float* ew3,
                           const float* ew4, const float* dw1, const float* dw2,
                           const float* dw3, const float* dw4,
                           float* wt_e1, float* wt_e2, float* wt_e3, float* wt_e4,
                           float* wt_d1, float* wtT_d2, float* wtT_d3, float* w4p)
{
    int idx = blockIdx.x*256 + threadIdx.x;
    if (idx < 3072)   { rp_conv(ew1, wt_e1, 3, 64, 16, idx); return; }
    idx -= 3072;
    if (idx < 131072) { rp_conv(ew2, wt_e2, 64, 128, 16, idx); return; }
    idx -= 131072;
    if (idx < 294912) { rp_conv(ew3, wt_e3, 128, 256, 9, idx); return; }
    idx -= 294912;
    if (idx < 589824) { rp_conv(ew4, wt_e4, 256, 256, 9, idx); return; }
    idx -= 589824;
    if (idx < 294912) { rp_conv(dw1, wt_d1, 256, 128, 9, idx); return; }
    idx -= 294912;
    if (idx < 131072) { rp_convT(dw2, wtT_d2, 128, 64, idx); return; }
    idx -= 131072;
    if (idx < 65536)  { rp_convT(dw3, wtT_d3, 64, 64, idx); return; }
    idx -= 65536;
    if (idx < 4096)   { rp_w4(dw4, w4p, idx); }
}

// ---------------------------------------------------------------------------
// Helpers
// ---------------------------------------------------------------------------
__global__ void cnorm_kernel(const float* __restrict__ cb, float* __restrict__ cn) {
    int row  = (blockIdx.x*blockDim.x + threadIdx.x) >> 5;
    int lane = threadIdx.x & 31;
    if (row >= 4096) return;
    const float* p = cb + (size_t)row*256;
    float s = 0.f;
    for (int c = lane; c < 256; c += 32) { float v = p[c]; s += v*v; }
#pragma unroll
    for (int o = 16; o; o >>= 1) s += __shfl_down_sync(0xffffffffu, s, o);
    if (!lane) cn[row] = s;
}

__global__ void zero_loss(double* l) { if (threadIdx.x < 4) l[threadIdx.x] = 0.0; }

__global__ void write_loss(const double* __restrict__ l, float* __restrict__ o) {
    if (threadIdx.x < 4)
        o[threadIdx.x] = (float)(l[threadIdx.x] * (1.0/(65536.0*256.0)));
}

__global__ void z_to_tokens(const float* __restrict__ z,
                            float* __restrict__ resid, float* __restrict__ qsum)
{
    __shared__ float t[32][33];
    int b  = blockIdx.z;
    int s0 = blockIdx.x*32;
    int c0 = blockIdx.y*32;
    int x  = threadIdx.x;
    for (int y = threadIdx.y; y < 32; y += 8)
        t[y][x] = z[((size_t)b*256 + c0 + y)*4096 + s0 + x];
    __syncthreads();
    for (int y = threadIdx.y; y < 32; y += 8) {
        size_t o = ((size_t)b*4096 + s0 + y)*256 + c0 + x;
        resid[o] = t[x][y];
        qsum[o]  = 0.f;
    }
}

__global__ void tokens_to_z(const float* __restrict__ qsum,
                            float* __restrict__ z1, float* __restrict__ z2)
{
    __shared__ float t[32][33];
    int b  = blockIdx.z;
    int c0 = blockIdx.x*32;
    int s0 = blockIdx.y*32;
    int x  = threadIdx.x;
    for (int y = threadIdx.y; y < 32; y += 8)
        t[y][x] = qsum[((size_t)b*4096 + s0 + y)*256 + c0 + x];
    __syncthreads();
    for (int y = threadIdx.y; y < 32; y += 8) {
        float v = t[x][y];
        size_t o = ((size_t)b*256 + c0 + y)*4096 + s0 + x;
        z1[o] = v; z2[o] = v;
    }
}

// ---------------------------------------------------------------------------
// Launch
// ---------------------------------------------------------------------------
extern "C" void kernel_launch(void* const* d_in, const int* in_sizes, int n_in,
                              void* d_out, int out_size)
{
    const float* x   = (const float*)d_in[0];
    const float* ew1 = (const float*)d_in[1];  const float* eb1 = (const float*)d_in[2];
    const float* ew2 = (const float*)d_in[3];  const float* eb2 = (const float*)d_in[4];
    const float* ew3 = (const float*)d_in[5];  const float* eb3 = (const float*)d_in[6];
    const float* ew4 = (const float*)d_in[7];  const float* eb4 = (const float*)d_in[8];
    const float* cbs = (const float*)d_in[9];
    const float* dw1 = (const float*)d_in[10]; const float* db1 = (const float*)d_in[11];
    const float* dw2 = (const float*)d_in[12]; const float* db2 = (const float*)d_in[13];
    const float* dw3 = (const float*)d_in[14]; const float* db3 = (const float*)d_in[15];
    const float* dw4 = (const float*)d_in[16]; const float* db4 = (const float*)d_in[17];
    float* out = (float*)d_out;

    float *h1, *h2, *h3, *z, *resid, *qsum, *cnorm, *w4p, *wt, *wtT, *d3;
    double* loss; unsigned* rowmin;
    cudaGetSymbolAddress((void**)&h1,    g_h1);
    cudaGetSymbolAddress((void**)&h2,    g_h2);
    cudaGetSymbolAddress((void**)&h3,    g_h3);
    cudaGetSymbolAddress((void**)&z,     g_z);
    cudaGetSymbolAddress((void**)&resid, g_resid);
    cudaGetSymbolAddress((void**)&qsum,  g_qsum);
    cudaGetSymbolAddress((void**)&loss,  g_loss);
    cudaGetSymbolAddress((void**)&cnorm, g_cnorm);
    cudaGetSymbolAddress((void**)&rowmin,g_rowmin);
    cudaGetSymbolAddress((void**)&w4p,   g_w4p);
    cudaGetSymbolAddress((void**)&wt,    g_wt);
    cudaGetSymbolAddress((void**)&wtT,   g_wtT);
    cudaGetSymbolAddress((void**)&d3,    g_d3);

    float* wt_e1  = wt;                               // 16*3*64    = 3072
    float* wt_e2  = wt + 3072;                        // 16*64*128  = 131072
    float* wt_e3  = wt_e2 + 131072;                   // 9*128*256  = 294912
    float* wt_e4  = wt_e3 + 294912;                   // 9*256*256  = 589824
    float* wt_d1  = wt_e4 + 589824;                   // 9*256*128  = 294912
    float* wtT_d2 = wtT;                              // 16*128*64  = 131072
    float* wtT_d3 = wtT + 131072;                     // 16*64*64   = 65536

    // output layout: recon | indices | commit_loss | quantized
    float* recO   = out;
    float* idxO   = out + 12582912;
    float* lossO  = idxO + 262144;
    float* quantO = lossO + 4;

    const int PA_SMEM  = 2*PLW*4 + 512;               // 34304
    const int CT4_SMEM = (16*792 + 1024)*4;           // 54784
    cudaFuncSetAttribute(vq_gemm_approx, cudaFuncAttributeMaxDynamicSharedMemorySize, PA_SMEM);
    cudaFuncSetAttribute(convT4_ffma,    cudaFuncAttributeMaxDynamicSharedMemorySize, CT4_SMEM);

    // prep
    repack_all     <<<5916, 256>>>(ew1, ew2, ew3, ew4, dw1, dw2, dw3, dw4,
                                   wt_e1, wt_e2, wt_e3, wt_e4, wt_d1,
                                   wtT_d2, wtT_d3, w4p);
    cnorm_kernel   <<<512, 256>>>(cbs, cnorm);
    zero_loss      <<<1, 32>>>(loss);
    init_rowmin_all<<<256, 1024>>>(rowmin);

    // ---- encoder (exact fp32) ----
    conv1_ffma<<<2048, 256>>>(x, wt_e1, eb1, h1);
    conv_ffma<4,2><<<dim3(512, 1), 256>>>(h1, wt_e2, eb2, h2,  64, 128, 128, 128, 1);
    conv_ffma<3,1><<<dim3(512, 2), 256>>>(h2, wt_e3, eb3, h3, 128,  64,  64, 256, 1);
    conv_ffma<3,1><<<dim3(512, 2), 256>>>(h3, wt_e4, eb4, z,  256,  64,  64, 256, 0);

    // ---- residual VQ: single-MMA tf32 approx distances (bf16 D) + exact rescore ----
    z_to_tokens<<<dim3(128, 8, 16), dim3(32, 8)>>>(z, resid, qsum);
    __nv_bfloat16* Dh = (__nv_bfloat16*)d3;
    for (int s = 0; s < 4; s++) {
        vq_gemm_approx  <<<dim3(512, 8), 256, PA_SMEM>>>(resid, cbs + (size_t)s*1024*256,
                                                         cnorm + s*1024, Dh, rowmin + s*65536);
        vq_select_update<<<8192, 256>>>(Dh, cbs + (size_t)s*1024*256, cnorm + s*1024,
                                        rowmin + s*65536, resid, qsum, idxO, s, loss);
    }
    write_loss <<<1, 32>>>(loss, lossO);
    tokens_to_z<<<dim3(8, 128, 16), dim3(32, 8)>>>(qsum, z, quantO);

    // ---- decoder (f32x2 FFMA, bit-exact) ----
    conv_ffma<3,1><<<dim3(512, 1), 256>>>(z, wt_d1, db1, h2, 256, 64, 64, 128, 1);
    convT_ffma<<<dim3( 256, 1, 4), 256>>>(h2, wtT_d2, db2, h1, 128,  64,  64, 6, 12);
    convT_ffma<<<dim3(1024, 1, 4), 256>>>(h1, wtT_d3, db3, d3,  64, 128, 128, 7, 14);
    convT4_ffma<<<4096, 256, CT4_SMEM>>>(d3, w4p, db4, recO);
}

// round 17
// speedup vs baseline: 1.0290x; 1.0082x over previous
#include <cuda_runtime.h>
#include <cuda_bf16.h>
#include <cstdint>

// ---------------------------------------------------------------------------
// Scratch (device globals — no allocation allowed)
// ---------------------------------------------------------------------------
__device__ float g_h1[16*64*128*128];          // enc1 out / dec2 out (reused)
__device__ float g_h2[16*128*64*64];           // enc2 out / dec1 out (reused)
__device__ float g_h3[16*256*64*64];           // enc3 out
__device__ float g_z [16*256*64*64];           // enc4 out (z) / quantized NCHW (reused)
__device__ float g_resid[65536*256];
__device__ float g_qsum [65536*256];
__device__ double g_loss[4];
__device__ float g_cnorm[4*1024];
__device__ unsigned g_rowmin[4*65536];
__device__ float g_w4p[64*16*4];               // dec_w4 repacked [ci][pt(16)][co pad 4]
__device__ float g_wt[1313792];                // conv weights repacked [tap][ci][co]
__device__ float g_wtT[196608];                // convT weights [parity][tap][ci][co]
__device__ float g_d3[16*64*256*256];          // dec3 out; ALSO the 65536x1024 D (bf16)

// ---------------------------------------------------------------------------
// tf32 helpers (approximate Phase-A path only; correctness never depends on it)
// ---------------------------------------------------------------------------
__device__ __forceinline__ uint32_t f2tf(float f) {
    uint32_t u;
    asm("cvt.rna.tf32.f32 %0, %1;" : "=r"(u) : "f"(f));
    return u;
}

__device__ __forceinline__ void mma_tf32(float* c, const uint32_t* a,
                                         uint32_t b0, uint32_t b1) {
    asm volatile(
        "mma.sync.aligned.m16n8k8.row.col.f32.tf32.tf32.f32 "
        "{%0,%1,%2,%3},{%4,%5,%6,%7},{%8,%9},{%0,%1,%2,%3};"
        : "+f"(c[0]), "+f"(c[1]), "+f"(c[2]), "+f"(c[3])
        : "r"(a[0]), "r"(a[1]), "r"(a[2]), "r"(a[3]), "r"(b0), "r"(b1));
}

// order-preserving float <-> uint32 (for atomicMin)
__device__ __forceinline__ unsigned fenc(float d) {
    unsigned u = __float_as_uint(d);
    return (u & 0x80000000u) ? ~u : (u | 0x80000000u);
}
__device__ __forceinline__ float fdec(unsigned e) {
    unsigned u = (e & 0x80000000u) ? (e & 0x7FFFFFFFu) : ~e;
    return __uint_as_float(u);
}

static const int PLW = 128*33;   // one smem plane in words (stride 33: conflict-free)

// ---------------------------------------------------------------------------
// Phase A: approximate distance matrix, single tf32 MMA, D stored as bf16.
// D[m,n] = cn[n] - 2 * R[m,:].cb[n,:]; per-row min -> rowmin (atomicMin).
// ---------------------------------------------------------------------------
__global__ __launch_bounds__(256)
void vq_gemm_approx(const float* __restrict__ R, const float* __restrict__ cb,
                    const float* __restrict__ cn, __nv_bfloat16* __restrict__ D,
                    unsigned* __restrict__ rowmin)
{
    extern __shared__ uint32_t dyn[];
    uint32_t* sA = dyn;
    uint32_t* sB = dyn + PLW;
    unsigned* sMin = (unsigned*)(dyn + 2*PLW);

    const int tid  = threadIdx.x;
    const int lane = tid & 31;
    const int warp = tid >> 5;
    const int wm = warp & 1;
    const int wn = warp >> 1;
    const int m0 = blockIdx.x << 7;
    const int n0 = blockIdx.y << 7;

    float acc[4][4][4];
#pragma unroll
    for (int i = 0; i < 4; i++)
#pragma unroll
        for (int j = 0; j < 4; j++)
#pragma unroll
            for (int k = 0; k < 4; k++) acc[i][j][k] = 0.f;

    if (tid < 128) sMin[tid] = 0xFFFFFFFFu;

    for (int k0 = 0; k0 < 256; k0 += 32) {
#pragma unroll
        for (int i = 0; i < 4; i++) {
            int idx4 = tid + i*256;
            int m  = idx4 >> 3;
            int kq = idx4 & 7;
            int oa = m*33 + kq*4;
            float4 a = *(const float4*)(R  + (size_t)(m0 + m)*256 + k0 + kq*4);
            sA[oa+0] = f2tf(a.x); sA[oa+1] = f2tf(a.y);
            sA[oa+2] = f2tf(a.z); sA[oa+3] = f2tf(a.w);
            float4 b = *(const float4*)(cb + (size_t)(n0 + m)*256 + k0 + kq*4);
            sB[oa+0] = f2tf(b.x); sB[oa+1] = f2tf(b.y);
            sB[oa+2] = f2tf(b.z); sB[oa+3] = f2tf(b.w);
        }
        __syncthreads();

#pragma unroll
        for (int ks = 0; ks < 4; ks++) {
            const int kb = ks*8 + (lane & 3);
            uint32_t bf[4][2];
#pragma unroll
            for (int fn = 0; fn < 4; fn++) {
                int n = wn*32 + fn*8 + (lane >> 2);
                bf[fn][0] = sB[n*33 + kb];  bf[fn][1] = sB[n*33 + kb + 4];
            }
#pragma unroll
            for (int fm = 0; fm < 4; fm++) {
                int r = wm*64 + fm*16 + (lane >> 2);
                uint32_t af[4];
                af[0] = sA[r*33 + kb];     af[1] = sA[(r+8)*33 + kb];
                af[2] = sA[r*33 + kb+4];   af[3] = sA[(r+8)*33 + kb+4];
#pragma unroll
                for (int fn = 0; fn < 4; fn++)
                    mma_tf32(acc[fm][fn], af, bf[fn][0], bf[fn][1]);
            }
        }
        __syncthreads();
    }

    float cnv[4][2];
#pragma unroll
    for (int fn = 0; fn < 4; fn++) {
        int col = n0 + wn*32 + fn*8 + 2*(lane & 3);
        cnv[fn][0] = cn[col];
        cnv[fn][1] = cn[col + 1];
    }
#pragma unroll
    for (int fm = 0; fm < 4; fm++) {
#pragma unroll
        for (int h = 0; h < 2; h++) {
            int rl = wm*64 + fm*16 + (lane >> 2) + h*8;
            int rg = m0 + rl;
            float mn = 3.402823466e38f;
#pragma unroll
            for (int fn = 0; fn < 4; fn++) {
                int col = n0 + wn*32 + fn*8 + 2*(lane & 3);
                float vx = cnv[fn][0] - 2.f*acc[fm][fn][h*2 + 0];
                float vy = cnv[fn][1] - 2.f*acc[fm][fn][h*2 + 1];
                mn = fminf(mn, fminf(vx, vy));
                *(__nv_bfloat162*)(D + (size_t)rg*1024 + col) =
                    __floats2bfloat162_rn(vx, vy);
            }
            atomicMin(&sMin[rl], fenc(mn));
        }
    }
    __syncthreads();
    if (tid < 128) atomicMin(&rowmin[m0 + tid], sMin[tid]);
}

// ---------------------------------------------------------------------------
// Phase B: one warp per token; batched bf16x2 scan (4 loads in flight),
// exact-FFMA rescore of candidates within EPS of the approx row-min,
// order-independent lowest-index tie-break, fused vq_update.
// EPS = 0.02 >= 3x the bound (bf16-D abs err <= 0.004, 2x mma err <= 0.002).
// ---------------------------------------------------------------------------
__global__ __launch_bounds__(256)
void vq_select_update(const __nv_bfloat16* __restrict__ D, const float* __restrict__ cb,
                      const float* __restrict__ cn,
                      const unsigned* __restrict__ rowmin,
                      float* __restrict__ resid, float* __restrict__ qsum,
                      float* __restrict__ idx_out, int stage,
                      double* __restrict__ lossAcc)
{
    __shared__ double sLoss[8];
    const int warp = threadIdx.x >> 5;
    const int lane = threadIdx.x & 31;
    const int t = blockIdx.x*8 + warp;

    const __nv_bfloat16* drow = D + (size_t)t*1024;
    const float thr = fdec(rowmin[t]) + 0.02f;

    float4 r0 = *(const float4*)(resid + (size_t)t*256 + lane*8);
    float4 r1 = *(const float4*)(resid + (size_t)t*256 + lane*8 + 4);

    float bestd = 3.402823466e38f;
    int   bestn = 0x7FFFFFFF;

    auto rescore = [&](int j) {
        const float* c = cb + (size_t)j*256;
        float4 c0 = *(const float4*)(c + lane*8);
        float4 c1 = *(const float4*)(c + lane*8 + 4);
        float dot = r0.x*c0.x + r0.y*c0.y + r0.z*c0.z + r0.w*c0.w
                  + r1.x*c1.x + r1.y*c1.y + r1.z*c1.z + r1.w*c1.w;
#pragma unroll
        for (int o = 16; o; o >>= 1)
            dot += __shfl_xor_sync(0xffffffffu, dot, o);
        float de = cn[j] - 2.f*dot;
        if (de < bestd || (de == bestd && j < bestn)) { bestd = de; bestn = j; }
    };

#pragma unroll
    for (int j0 = 0; j0 < 1024; j0 += 256) {
        float2 dd[4];
#pragma unroll
        for (int u = 0; u < 4; u++) {
            __nv_bfloat162 dv2 =
                *(const __nv_bfloat162*)(drow + j0 + u*64 + lane*2);
            dd[u] = __bfloat1622float2(dv2);
        }
#pragma unroll
        for (int u = 0; u < 4; u++) {
            unsigned me = __ballot_sync(0xffffffffu, dd[u].x <= thr);
            unsigned mo = __ballot_sync(0xffffffffu, dd[u].y <= thr);
            while (me) { int s = __ffs(me) - 1; me &= me - 1; rescore(j0 + u*64 + 2*s); }
            while (mo) { int s = __ffs(mo) - 1; mo &= mo - 1; rescore(j0 + u*64 + 2*s + 1); }
        }
    }

    const float* q = cb + (size_t)bestn*256;
    float4 q0 = *(const float4*)(q + lane*8);
    float4 q1 = *(const float4*)(q + lane*8 + 4);
    float4 s0 = *(float4*)(qsum + (size_t)t*256 + lane*8);
    float4 s1 = *(float4*)(qsum + (size_t)t*256 + lane*8 + 4);

    float ls = 0.f;
    {
        float d;
        d = q0.x-r0.x; ls += d*d;  d = q0.y-r0.y; ls += d*d;
        d = q0.z-r0.z; ls += d*d;  d = q0.w-r0.w; ls += d*d;
        d = q1.x-r1.x; ls += d*d;  d = q1.y-r1.y; ls += d*d;
        d = q1.z-r1.z; ls += d*d;  d = q1.w-r1.w; ls += d*d;
    }
    s0.x += q0.x; s0.y += q0.y; s0.z += q0.z; s0.w += q0.w;
    s1.x += q1.x; s1.y += q1.y; s1.z += q1.z; s1.w += q1.w;
    r0.x -= q0.x; r0.y -= q0.y; r0.z -= q0.z; r0.w -= q0.w;
    r1.x -= q1.x; r1.y -= q1.y; r1.z -= q1.z; r1.w -= q1.w;
    *(float4*)(qsum  + (size_t)t*256 + lane*8)     = s0;
    *(float4*)(qsum  + (size_t)t*256 + lane*8 + 4) = s1;
    *(float4*)(resid + (size_t)t*256 + lane*8)     = r0;
    *(float4*)(resid + (size_t)t*256 + lane*8 + 4) = r1;

#pragma unroll
    for (int o = 16; o; o >>= 1) ls += __shfl_down_sync(0xffffffffu, ls, o);
    if (lane == 0) {
        sLoss[warp] = (double)ls;
        idx_out[(t >> 12)*16384 + stage*4096 + (t & 4095)] = (float)bestn;
    }
    __syncthreads();
    if (threadIdx.x == 0) {
        double tot = 0.0;
#pragma unroll
        for (int w = 0; w < 8; w++) tot += sLoss[w];
        atomicAdd(lossAcc + stage, tot);
    }
}

// ---------------------------------------------------------------------------
// enc1 (4x4 s2 p1, Cin=3 -> Cout=64) as implicit GEMM. M=128 px (one output
// row), N=64, K=48 (16 taps x 3 ci), single smem stage. Coalesced stores.
// ---------------------------------------------------------------------------
__global__ __launch_bounds__(256)
void conv1_ffma(const float* __restrict__ in, const float* __restrict__ wt,
                const float* __restrict__ bias, float* __restrict__ out)
{
    __shared__ float sA[48*128];
    __shared__ float sB[48*64];
    const int tid = threadIdx.x;
    const int tx = tid & 31;
    const int ty = tid >> 5;
    const int b  = blockIdx.x >> 7;
    const int yr = blockIdx.x & 127;

    for (int idx = tid; idx < 48*128; idx += 256) {
        int k  = idx >> 7, px = idx & 127;
        int tap = k/3, ci = k - tap*3;
        int kh = tap >> 2, kw = tap & 3;
        int iy = yr*2 + kh - 1;
        int ix = px*2 + kw - 1;
        float v = 0.f;
        if ((unsigned)iy < 256u && (unsigned)ix < 256u)
            v = in[((size_t)(b*3 + ci)*256 + iy)*256 + ix];
        sA[idx] = v;
    }
    for (int idx = tid; idx < 48*64; idx += 256)
        sB[idx] = wt[idx];
    __syncthreads();

    float acc[4][8];
#pragma unroll
    for (int i = 0; i < 4; i++)
#pragma unroll
        for (int j = 0; j < 8; j++) acc[i][j] = 0.f;

#pragma unroll
    for (int kk = 0; kk < 48; kk++) {
        float av[4];
#pragma unroll
        for (int i = 0; i < 4; i++) av[i] = sA[kk*128 + tx + 32*i];
        float4 b0 = *(const float4*)&sB[kk*64 + ty*8];
        float4 b1 = *(const float4*)&sB[kk*64 + ty*8 + 4];
        float bv[8] = {b0.x,b0.y,b0.z,b0.w,b1.x,b1.y,b1.z,b1.w};
#pragma unroll
        for (int i = 0; i < 4; i++)
#pragma unroll
            for (int j = 0; j < 8; j++) acc[i][j] += av[i]*bv[j];
    }

#pragma unroll
    for (int j = 0; j < 8; j++) {
        int co = ty*8 + j;
        float bv = bias[co];
        float* p = out + ((size_t)(b*64 + co)*128 + yr)*128;
#pragma unroll
        for (int i = 0; i < 4; i++)
            p[tx + 32*i] = fmaxf(acc[i][j] + bv, 0.f);
    }
}

// ---------------------------------------------------------------------------
// Implicit-GEMM FFMA conv (3x3 s1 or 4x4 s2, pad 1). Output 64x64 per image.
// Double-buffered smem, register-staged prefetch, single sync per chunk.
// ---------------------------------------------------------------------------
template<int KSZ, int S>
__global__ __launch_bounds__(256, 2)
void conv_ffma(const float* __restrict__ in, const float* __restrict__ wt,
               const float* __restrict__ bias, float* __restrict__ out,
               int Cin, int Hin, int Win, int Cout, int relu)
{
    __shared__ float sA[2][16*128];
    __shared__ float sB[2][16*128];
    const int tid = threadIdx.x;
    const int tx = tid & 15;
    const int ty = tid >> 4;
    const int m0  = blockIdx.x << 7;
    const int co0 = blockIdx.y << 7;
    const int b   = m0 >> 12;
    const int y0  = (m0 & 4095) >> 6;
    const int cpt = Cin >> 4;
    const int NCH = KSZ*KSZ*cpt;

    float acc[8][8];
#pragma unroll
    for (int i = 0; i < 8; i++)
#pragma unroll
        for (int j = 0; j < 8; j++) acc[i][j] = 0.f;

    float ra[8], rb[8];

    auto loadc = [&](int q) {
        int tap = q / cpt;
        int ci0 = (q - tap*cpt) << 4;
        int dy = tap/KSZ - 1, dx = tap%KSZ - 1;
#pragma unroll
        for (int v = 0; v < 8; v++) {
            int idx = tid + v*256;
            int ci = idx >> 7, pix = idx & 127;
            int iy = (y0 + (pix >> 6))*S + dy;
            int ix = (pix & 63)*S + dx;
            float val = 0.f;
            if ((unsigned)iy < (unsigned)Hin && (unsigned)ix < (unsigned)Win)
                val = in[((size_t)(b*Cin + ci0 + ci)*Hin + iy)*Win + ix];
            ra[v] = val;
            rb[v] = wt[((size_t)tap*Cin + ci0 + ci)*Cout + co0 + pix];
        }
    };
    auto storec = [&](int buf) {
#pragma unroll
        for (int v = 0; v < 8; v++) {
            int idx = tid + v*256;
            int ci = idx >> 7, pix = idx & 127;
            sA[buf][ci*128 + pix] = ra[v];
            sB[buf][ci*128 + pix] = rb[v];
        }
    };

    loadc(0); storec(0); __syncthreads();
    for (int q = 0; q < NCH; q++) {
        if (q + 1 < NCH) loadc(q + 1);
        const float* pA = sA[q & 1];
        const float* pB = sB[q & 1];
#pragma unroll
        for (int kk = 0; kk < 16; kk++) {
            float4 a0 = *(const float4*)&pA[kk*128 + tx*8];
            float4 a1 = *(const float4*)&pA[kk*128 + tx*8 + 4];
            float4 b0 = *(const float4*)&pB[kk*128 + ty*8];
            float4 b1 = *(const float4*)&pB[kk*128 + ty*8 + 4];
            float av[8] = {a0.x,a0.y,a0.z,a0.w,a1.x,a1.y,a1.z,a1.w};
            float bv[8] = {b0.x,b0.y,b0.z,b0.w,b1.x,b1.y,b1.z,b1.w};
#pragma unroll
            for (int i = 0; i < 8; i++)
#pragma unroll
                for (int j = 0; j < 8; j++) acc[i][j] += av[i]*bv[j];
        }
        if (q + 1 < NCH) storec((q + 1) & 1);
        __syncthreads();
    }

    const int yr = y0 + (tx >> 3);
    const int xc = (tx*8) & 63;
#pragma unroll
    for (int j = 0; j < 8; j++) {
        int co = co0 + ty*8 + j;
        float bv = bias[co];
        float4 v0, v1;
        v0.x = acc[0][j]+bv; v0.y = acc[1][j]+bv; v0.z = acc[2][j]+bv; v0.w = acc[3][j]+bv;
        v1.x = acc[4][j]+bv; v1.y = acc[5][j]+bv; v1.z = acc[6][j]+bv; v1.w = acc[7][j]+bv;
        if (relu) {
            v0.x = fmaxf(v0.x,0.f); v0.y = fmaxf(v0.y,0.f); v0.z = fmaxf(v0.z,0.f); v0.w = fmaxf(v0.w,0.f);
            v1.x = fmaxf(v1.x,0.f); v1.y = fmaxf(v1.y,0.f); v1.z = fmaxf(v1.z,0.f); v1.w = fmaxf(v1.w,0.f);
        }
        float* p = out + ((size_t)(b*Cout + co)*4096 + yr*64 + xc);
        *(float4*)p = v0;
        *(float4*)(p + 4) = v1;
    }
}

// ---------------------------------------------------------------------------
// Implicit-GEMM FFMA convT (k4 s2 p1), parity-decomposed, Cout=64, relu.
// Coalesced parity stores (mx = tx + 32*i).
// ---------------------------------------------------------------------------
__global__ __launch_bounds__(256, 2)
void convT_ffma(const float* __restrict__ in, const float* __restrict__ wtT,
                const float* __restrict__ bias, float* __restrict__ out,
                int Cin, int Hin, int Win, int wsh, int hwsh)
{
    __shared__ float sA[2][16*256];
    __shared__ float sB[2][16*64];
    const int tid = threadIdx.x;
    const int tx = tid & 31;
    const int ty = tid >> 5;
    const int P0 = blockIdx.x << 8;
    const int b   = P0 >> hwsh;
    const int lp  = P0 & ((1 << hwsh) - 1);
    const int my0 = lp >> wsh;
    const int p  = blockIdx.z;
    const int ey = p >> 1, ex = p & 1;
    const float* wtp = wtT + (size_t)p*4*Cin*64;
    const int Wo  = Win*2;
    const int HWo = (Hin*Win)*4;
    const int cpt = Cin >> 4;
    const int NCH = 4*cpt;

    float acc[8][8];
#pragma unroll
    for (int i = 0; i < 8; i++)
#pragma unroll
        for (int j = 0; j < 8; j++) acc[i][j] = 0.f;

    float ra[16], rb[4];

    auto loadc = [&](int q) {
        int t = q / cpt;
        int ci0 = (q - t*cpt) << 4;
        int jy = t >> 1, jx = t & 1;
        int ry = (ey == 0) ? (jy == 0 ? 0 : -1) : (jy == 0 ? 1 : 0);
        int rx = (ex == 0) ? (jx == 0 ? 0 : -1) : (jx == 0 ? 1 : 0);
#pragma unroll
        for (int v = 0; v < 16; v++) {
            int idx = tid + v*256;
            int ci = idx >> 8, pix = idx & 255;
            int iy = my0 + (pix >> wsh) + ry;
            int ix = (pix & (Win-1)) + rx;
            float val = 0.f;
            if ((unsigned)iy < (unsigned)Hin && (unsigned)ix < (unsigned)Win)
                val = in[((size_t)(b*Cin + ci0 + ci)*Hin + iy)*Win + ix];
            ra[v] = val;
        }
#pragma unroll
        for (int v = 0; v < 4; v++) {
            int idx = tid + v*256;
            int ci = idx >> 6, n = idx & 63;
            rb[v] = wtp[((size_t)t*Cin + ci0 + ci)*64 + n];
        }
    };
    auto storec = [&](int buf) {
#pragma unroll
        for (int v = 0; v < 16; v++) {
            int idx = tid + v*256;
            int ci = idx >> 8, pix = idx & 255;
            sA[buf][ci*256 + pix] = ra[v];
        }
#pragma unroll
        for (int v = 0; v < 4; v++) {
            int idx = tid + v*256;
            int ci = idx >> 6, n = idx & 63;
            sB[buf][ci*64 + n] = rb[v];
        }
    };

    loadc(0); storec(0); __syncthreads();
    for (int q = 0; q < NCH; q++) {
        if (q + 1 < NCH) loadc(q + 1);
        const float* pA = sA[q & 1];
        const float* pB = sB[q & 1];
#pragma unroll
        for (int kk = 0; kk < 16; kk++) {
            float av[8];
#pragma unroll
            for (int i = 0; i < 8; i++)
                av[i] = pA[kk*256 + tx + 32*i];
            float4 b0 = *(const float4*)&pB[kk*64 + ty*8];
            float4 b1 = *(const float4*)&pB[kk*64 + ty*8 + 4];
            float bv[8] = {b0.x,b0.y,b0.z,b0.w,b1.x,b1.y,b1.z,b1.w};
#pragma unroll
            for (int i = 0; i < 8; i++)
#pragma unroll
                for (int j = 0; j < 8; j++) acc[i][j] += av[i]*bv[j];
        }
        if (q + 1 < NCH) storec((q + 1) & 1);
        __syncthreads();
    }

#pragma unroll
    for (int j = 0; j < 8; j++) {
        int co = ty*8 + j;
        float bv = bias[co];
        float* pb = out + (size_t)(b*64 + co)*HWo + ex;
#pragma unroll
        for (int i = 0; i < 8; i++) {
            int gp = lp + tx + 32*i;
            int my = gp >> wsh;
            int mx = gp & (Win-1);
            int oy = 2*my + ey;
            pb[oy*Wo + 2*mx] = fmaxf(acc[i][j] + bv, 0.f);
        }
    }
}

// ---------------------------------------------------------------------------
// convT4 (k4 s2 p1, Cin=64 -> Cout=3, tanh): per-parity 4-tap form.
// Weights wp[ci][pt(16)][co pad 4]. Dynamic smem 54784 B.
// ---------------------------------------------------------------------------
__global__ __launch_bounds__(256)
void convT4_ffma(const float* __restrict__ in, const float* __restrict__ wp,
                 const float* __restrict__ bias, float* __restrict__ out)
{
    extern __shared__ float dynf[];
    float* sA = dynf;              // [16 ci][3 rows][264]
    float* sB = dynf + 16*792;     // [16 ci][16 pt][4]

    const int tid = threadIdx.x;
    const int b  = blockIdx.x >> 8;
    const int my = blockIdx.x & 255;
    const float* inb = in + (size_t)b*64*65536;

    float acc[12];
#pragma unroll
    for (int i = 0; i < 12; i++) acc[i] = 0.f;

    for (int ci0 = 0; ci0 < 64; ci0 += 16) {
        for (int idx = tid; idx < 16*3*258; idx += 256) {
            int ci = idx / 774;
            int rem = idx - ci*774;
            int r = rem / 258, c = rem - r*258;
            int iy = my - 1 + r, ix = c - 1;
            float v = 0.f;
            if ((unsigned)iy < 256u && (unsigned)ix < 256u)
                v = inb[((size_t)(ci0 + ci)*256 + iy)*256 + ix];
            sA[ci*792 + r*264 + c] = v;
        }
        for (int idx = tid; idx < 1024; idx += 256)
            sB[idx] = wp[ci0*64 + idx];
        __syncthreads();

        for (int ci = 0; ci < 16; ci++) {
            float n[9];
#pragma unroll
            for (int r = 0; r < 3; r++)
#pragma unroll
                for (int c = 0; c < 3; c++)
                    n[r*3 + c] = sA[ci*792 + r*264 + c + tid];
#pragma unroll
            for (int pt = 0; pt < 16; pt++) {
                const int p = pt >> 2, t = pt & 3;
                const int ey = p >> 1, ex = p & 1;
                const int jy = t >> 1, jx = t & 1;
                const int ry = (ey == 0) ? (jy == 0 ? 0 : -1) : (jy == 0 ? 1 : 0);
                const int rx = (ex == 0) ? (jx == 0 ? 0 : -1) : (jx == 0 ? 1 : 0);
                const int ni = (1 + ry)*3 + (1 + rx);
                float a = n[ni];
                const float4 w = *(const float4*)&sB[ci*64 + pt*4];
                acc[p*3 + 0] += a*w.x;
                acc[p*3 + 1] += a*w.y;
                acc[p*3 + 2] += a*w.z;
            }
        }
        __syncthreads();
    }

    const int mx = tid;
#pragma unroll
    for (int p = 0; p < 4; p++) {
        int ey = p >> 1, ex = p & 1;
        int oy = 2*my + ey;
#pragma unroll
        for (int co = 0; co < 3; co++) {
            float v = tanhf(acc[p*3 + co] + bias[co]);
            out[(((size_t)b*3 + co)*512 + oy)*512 + 2*mx + ex] = v;
        }
    }
}

// ---------------------------------------------------------------------------
// Fused prep kernel: weight repacks + codebook norms + loss/rowmin init
// ---------------------------------------------------------------------------
__device__ __forceinline__ void rp_conv(const float* w, float* wt,
                                        int Cin, int Cout, int KK, int idx)
{
    int co = idx % Cout; int r = idx / Cout;
    int ci = r % Cin;    int tap = r / Cin;
    wt[idx] = w[(co*Cin + ci)*KK + tap];
}

__device__ __forceinline__ void rp_convT(const float* w, float* wtT,
                                         int Cin, int Cout, int idx)
{
    int co = idx % Cout; int r = idx / Cout;
    int ci = r % Cin;    int pt = r / Cin;
    int p = pt >> 2, t = pt & 3;
    int ey = p >> 1, ex = p & 1;
    int jy = t >> 1, jx = t & 1;
    int ky = (ey == 0) ? (jy == 0 ? 1 : 3) : (jy == 0 ? 0 : 2);
    int kx = (ex == 0) ? (jx == 0 ? 1 : 3) : (jx == 0 ? 0 : 2);
    wtT[idx] = w[((ci*Cout + co)*4 + ky)*4 + kx];
}

__device__ __forceinline__ void rp_w4(const float* w, float* wp, int idx)
{
    int ci = idx >> 6;
    int rem = idx & 63;
    int pt = rem >> 2, c = rem & 3;
    float v = 0.f;
    if (c < 3) {
        int p = pt >> 2, t = pt & 3;
        int ey = p >> 1, ex = p & 1;
        int jy = t >> 1, jx = t & 1;
        int ky = (ey == 0) ? (jy == 0 ? 1 : 3) : (jy == 0 ? 0 : 2);
        int kx = (ex == 0) ? (jx == 0 ? 1 : 3) : (jx == 0 ? 0 : 2);
        v = w[((ci*3 + c)*4 + ky)*4 + kx];
    }
    wp[idx] = v;
}

// region sizes (threads):
//  repacks: 3072 + 131072 + 294912 + 589824 + 294912 + 131072 + 65536 + 4096 = 1514496
//  rowmin init: 262144    loss init: 32 (first block of that region)
//  cnorm: 4096 rows * 32 lanes = 131072
// total = 1907712 threads -> 7452 blocks of 256
__global__ void prep_all(const float* ew1, const float* ew2, const float* ew3,
                         const float* ew4, const float* dw1, const float* dw2,
                         const float* dw3, const float* dw4, const float* cbs,
                         float* wt_e1, float* wt_e2, float* wt_e3, float* wt_e4,
                         float* wt_d1, float* wtT_d2, float* wtT_d3, float* w4p,
                         unsigned* rowmin, double* loss, float* cn)
{
    int idx = blockIdx.x*256 + threadIdx.x;
    if (idx < 3072)   { rp_conv(ew1, wt_e1, 3, 64, 16, idx); return; }
    idx -= 3072;
    if (idx < 131072) { rp_conv(ew2, wt_e2, 64, 128, 16, idx); return; }
    idx -= 131072;
    if (idx < 294912) { rp_conv(ew3, wt_e3, 128, 256, 9, idx); return; }
    idx -= 294912;
    if (idx < 589824) { rp_conv(ew4, wt_e4, 256, 256, 9, idx); return; }
    idx -= 589824;
    if (idx < 294912) { rp_conv(dw1, wt_d1, 256, 128, 9, idx); return; }
    idx -= 294912;
    if (idx < 131072) { rp_convT(dw2, wtT_d2, 128, 64, idx); return; }
    idx -= 131072;
    if (idx < 65536)  { rp_convT(dw3, wtT_d3, 64, 64, idx); return; }
    idx -= 65536;
    if (idx < 4096)   { rp_w4(dw4, w4p, idx); return; }
    idx -= 4096;
    if (idx < 262144) {
        rowmin[idx] = 0xFFFFFFFFu;
        if (idx < 4) loss[idx] = 0.0;
        return;
    }
    idx -= 262144;
    if (idx < 131072) {
        int row  = idx >> 5;
        int lane = threadIdx.x & 31;   // region is 32-aligned within blocks
        const float* p = cbs + (size_t)row*256;
        float s = 0.f;
        for (int c = lane; c < 256; c += 32) { float v = p[c]; s += v*v; }
#pragma unroll
        for (int o = 16; o; o >>= 1) s += __shfl_down_sync(0xffffffffu, s, o);
        if (!lane) cn[row] = s;
    }
}

__global__ void write_loss(const double* __restrict__ l, float* __restrict__ o) {
    if (threadIdx.x < 4)
        o[threadIdx.x] = (float)(l[threadIdx.x] * (1.0/(65536.0*256.0)));
}

__global__ void z_to_tokens(const float* __restrict__ z,
                            float* __restrict__ resid, float* __restrict__ qsum)
{
    __shared__ float t[32][33];
    int b  = blockIdx.z;
    int s0 = blockIdx.x*32;
    int c0 = blockIdx.y*32;
    int x  = threadIdx.x;
    for (int y = threadIdx.y; y < 32; y += 8)
        t[y][x] = z[((size_t)b*256 + c0 + y)*4096 + s0 + x];
    __syncthreads();
    for (int y = threadIdx.y; y < 32; y += 8) {
        size_t o = ((size_t)b*4096 + s0 + y)*256 + c0 + x;
        resid[o] = t[x][y];
        qsum[o]  = 0.f;
    }
}

__global__ void tokens_to_z(const float* __restrict__ qsum,
                            float* __restrict__ z1, float* __restrict__ z2)
{
    __shared__ float t[32][33];
    int b  = blockIdx.z;
    int c0 = blockIdx.x*32;
    int s0 = blockIdx.y*32;
    int x  = threadIdx.x;
    for (int y = threadIdx.y; y < 32; y += 8)
        t[y][x] = qsum[((size_t)b*4096 + s0 + y)*256 + c0 + x];
    __syncthreads();
    for (int y = threadIdx.y; y < 32; y += 8) {
        float v = t[x][y];
        size_t o = ((size_t)b*256 + c0 + y)*4096 + s0 + x;
        z1[o] = v; z2[o] = v;
    }
}

// ---------------------------------------------------------------------------
// Launch
// ---------------------------------------------------------------------------
extern "C" void kernel_launch(void* const* d_in, const int* in_sizes, int n_in,
                              void* d_out, int out_size)
{
    const float* x   = (const float*)d_in[0];
    const float* ew1 = (const float*)d_in[1];  const float* eb1 = (const float*)d_in[2];
    const float* ew2 = (const float*)d_in[3];  const float* eb2 = (const float*)d_in[4];
    const float* ew3 = (const float*)d_in[5];  const float* eb3 = (const float*)d_in[6];
    const float* ew4 = (const float*)d_in[7];  const float* eb4 = (const float*)d_in[8];
    const float* cbs = (const float*)d_in[9];
    const float* dw1 = (const float*)d_in[10]; const float* db1 = (const float*)d_in[11];
    const float* dw2 = (const float*)d_in[12]; const float* db2 = (const float*)d_in[13];
    const float* dw3 = (const float*)d_in[14]; const float* db3 = (const float*)d_in[15];
    const float* dw4 = (const float*)d_in[16]; const float* db4 = (const float*)d_in[17];
    float* out = (float*)d_out;

    float *h1, *h2, *h3, *z, *resid, *qsum, *cnorm, *w4p, *wt, *wtT, *d3;
    double* loss; unsigned* rowmin;
    cudaGetSymbolAddress((void**)&h1,    g_h1);
    cudaGetSymbolAddress((void**)&h2,    g_h2);
    cudaGetSymbolAddress((void**)&h3,    g_h3);
    cudaGetSymbolAddress((void**)&z,     g_z);
    cudaGetSymbolAddress((void**)&resid, g_resid);
    cudaGetSymbolAddress((void**)&qsum,  g_qsum);
    cudaGetSymbolAddress((void**)&loss,  g_loss);
    cudaGetSymbolAddress((void**)&cnorm, g_cnorm);
    cudaGetSymbolAddress((void**)&rowmin,g_rowmin);
    cudaGetSymbolAddress((void**)&w4p,   g_w4p);
    cudaGetSymbolAddress((void**)&wt,    g_wt);
    cudaGetSymbolAddress((void**)&wtT,   g_wtT);
    cudaGetSymbolAddress((void**)&d3,    g_d3);

    float* wt_e1  = wt;                               // 16*3*64    = 3072
    float* wt_e2  = wt + 3072;                        // 16*64*128  = 131072
    float* wt_e3  = wt_e2 + 131072;                   // 9*128*256  = 294912
    float* wt_e4  = wt_e3 + 294912;                   // 9*256*256  = 589824
    float* wt_d1  = wt_e4 + 589824;                   // 9*256*128  = 294912
    float* wtT_d2 = wtT;                              // 16*128*64  = 131072
    float* wtT_d3 = wtT + 131072;                     // 16*64*64   = 65536

    // output layout: recon | indices | commit_loss | quantized
    float* recO   = out;
    float* idxO   = out + 12582912;
    float* lossO  = idxO + 262144;
    float* quantO = lossO + 4;

    const int PA_SMEM  = 2*PLW*4 + 512;               // 34304
    const int CT4_SMEM = (16*792 + 1024)*4;           // 54784
    cudaFuncSetAttribute(vq_gemm_approx, cudaFuncAttributeMaxDynamicSharedMemorySize, PA_SMEM);
    cudaFuncSetAttribute(convT4_ffma,    cudaFuncAttributeMaxDynamicSharedMemorySize, CT4_SMEM);

    // prep (single fused launch: repacks + rowmin/loss init + cnorm)
    prep_all<<<7452, 256>>>(ew1, ew2, ew3, ew4, dw1, dw2, dw3, dw4, cbs,
                            wt_e1, wt_e2, wt_e3, wt_e4, wt_d1,
                            wtT_d2, wtT_d3, w4p, rowmin, loss, cnorm);

    // ---- encoder (exact fp32) ----
    conv1_ffma<<<2048, 256>>>(x, wt_e1, eb1, h1);
    conv_ffma<4,2><<<dim3(512, 1), 256>>>(h1, wt_e2, eb2, h2,  64, 128, 128, 128, 1);
    conv_ffma<3,1><<<dim3(512, 2), 256>>>(h2, wt_e3, eb3, h3, 128,  64,  64, 256, 1);
    conv_ffma<3,1><<<dim3(512, 2), 256>>>(h3, wt_e4, eb4, z,  256,  64,  64, 256, 0);

    // ---- residual VQ: single-MMA tf32 approx distances (bf16 D) + exact rescore ----
    z_to_tokens<<<dim3(128, 8, 16), dim3(32, 8)>>>(z, resid, qsum);
    __nv_bfloat16* Dh = (__nv_bfloat16*)d3;
    for (int s = 0; s < 4; s++) {
        vq_gemm_approx  <<<dim3(512, 8), 256, PA_SMEM>>>(resid, cbs + (size_t)s*1024*256,
                                                         cnorm + s*1024, Dh, rowmin + s*65536);
        vq_select_update<<<8192, 256>>>(Dh, cbs + (size_t)s*1024*256, cnorm + s*1024,
                                        rowmin + s*65536, resid, qsum, idxO, s, loss);
    }
    write_loss <<<1, 32>>>(loss, lossO);
    tokens_to_z<<<dim3(8, 128, 16), dim3(32, 8)>>>(qsum, z, quantO);

    // ---- decoder (FFMA, exact) ----
    conv_ffma<3,1><<<dim3(512, 1), 256>>>(z, wt_d1, db1, h2, 256, 64, 64, 128, 1);
    convT_ffma<<<dim3( 256, 1, 4), 256>>>(h2, wtT_d2, db2, h1, 128,  64,  64, 6, 12);
    convT_ffma<<<dim3(1024, 1, 4), 256>>>(h1, wtT_d3, db3, d3,  64, 128, 128, 7, 14);
    convT4_ffma<<<4096, 256, CT4_SMEM>>>(d3, w4p, db4, recO);
}